// round 11
// baseline (speedup 1.0000x reference)
#include <cuda_runtime.h>
#include <cuda_fp16.h>
#include <cuda_bf16.h>
#include <cstdint>

#define N_NODES 100000
#define VF      128
#define FILT    64
#define NH      3
#define KNBR    10
#define ZC      192
#define NCOLS   384
#define OUTC    192

// ---------------- scratch (static device globals) --------------------------
__device__ __half         g_Zch[2][(size_t)N_NODES * ZC];   // fp16, compacted
__device__ __nv_bfloat16  g_Znh[2][(size_t)N_NODES * ZC];   // bf16, compacted
__device__ uint32_t       g_Bh[2][(VF / 2) * NCOLS];        // fp16x2 packed [k2][c]
__device__ float          g_w1[2][NH * VF];
__device__ float          g_w2[2][NH * VF];
__device__ int4           g_meta[N_NODES];   // {(pos<<1)|b, s1h0, s1h1, s1h2}
__device__ float4         g_s2v[N_NODES];    // {s2h0, s2h1, s2h2, bits((pos<<1)|b)}
__device__ uint4          g_rec[2][(size_t)N_NODES * KNBR]; // {off, p0, p1, p2}
__device__ float4         g_hdr[2][N_NODES]; // {rs0, rs1, rs2, bits(cg|(pb<<4))}
__device__ int            g_perm[2][N_NODES];
__device__ int            g_cnt[2];

// ---------------- helpers ----------------------------------------------------
__device__ __forceinline__ void mma_f16(float (&d)[4], const uint32_t (&a)[4],
                                        const uint32_t (&b)[2]) {
    asm volatile(
        "mma.sync.aligned.m16n8k16.row.col.f32.f16.f16.f32 "
        "{%0,%1,%2,%3}, {%4,%5,%6,%7}, {%8,%9}, {%0,%1,%2,%3};"
        : "+f"(d[0]), "+f"(d[1]), "+f"(d[2]), "+f"(d[3])
        : "r"(a[0]), "r"(a[1]), "r"(a[2]), "r"(a[3]), "r"(b[0]), "r"(b[1]));
}
__device__ __forceinline__ uint32_t smem_u32(const void* p) {
    uint32_t a;
    asm("{ .reg .u64 t; cvta.to.shared.u64 t, %1; cvt.u32.u64 %0, t; }"
        : "=r"(a) : "l"(p));
    return a;
}
__device__ __forceinline__ void cp_async16(uint32_t saddr, const void* g) {
    asm volatile("cp.async.cg.shared.global [%0], [%1], 16;"
                 :: "r"(saddr), "l"(g) : "memory");
}
#define CP_COMMIT() asm volatile("cp.async.commit_group;" ::: "memory")
#define CP_WAIT(n)  asm volatile("cp.async.wait_group %0;" :: "n"(n) : "memory")
__device__ __forceinline__ uint32_t pack_bf16x2(float lo, float hi) {
    uint32_t r;
    asm("cvt.rn.bf16x2.f32 %0, %1, %2;" : "=r"(r) : "f"(hi), "f"(lo));
    return r;
}
__device__ __forceinline__ uint32_t pack_f16x2(float lo, float hi) {
    __half2 h = __floats2half2_rn(lo, hi);
    return *(uint32_t*)&h;
}
// bf16x2 -> packed f32x2 (low elem in low word)
__device__ __forceinline__ unsigned long long bf2_f32x2(uint32_t u) {
    unsigned long long r;
    uint32_t lo = u << 16;
    uint32_t hi = u & 0xffff0000u;
    asm("mov.b64 %0, {%1, %2};" : "=l"(r) : "r"(lo), "r"(hi));
    return r;
}
#define FMA2(acc, a, b) \
    asm("fma.rn.f32x2 %0, %1, %2, %0;" : "+l"(acc) : "l"(a), "l"(b))

// ---------------- reset -------------------------------------------------------
__global__ void reset_kernel() {
    if (threadIdx.x == 0) { g_cnt[0] = 0; g_cnt[1] = 0; }
}

// ---------------- fused setup: prepack | wvec | compact -------------------------
__global__ void setup_kernel(const float* __restrict__ Wvc0, const float* __restrict__ Wvn0,
                             const float* __restrict__ a0,
                             const float* __restrict__ Wvc1, const float* __restrict__ Wvn1,
                             const float* __restrict__ a1,
                             const int* __restrict__ is_int) {
    const int bid = blockIdx.x;
    if (bid < 192) {
        const int branch = bid >= 96;
        const float* Wvc = branch ? Wvc1 : Wvc0;
        const float* Wvn = branch ? Wvn1 : Wvn0;
        int i = (bid - branch * 96) * 256 + threadIdx.x;     // < 24576
        int k2 = i / NCOLS, c = i % NCOLS;
        const float* W;
        int h, o;
        if (c < ZC) { W = Wvc; h = c / FILT; o = c % FILT; }
        else        { W = Wvn; h = (c - ZC) / FILT; o = (c - ZC) % FILT; }
        float v0 = W[((size_t)h * VF + 2 * k2) * FILT + o];
        float v1 = W[((size_t)h * VF + 2 * k2 + 1) * FILT + o];
        g_Bh[branch][i] = pack_f16x2(v0, v1);
    } else if (bid < 288) {
        int w = (bid - 192) * 8 + (threadIdx.x >> 5);        // < 768
        int lane = threadIdx.x & 31;
        const int branch = w >= NH * VF;
        int gw = w - branch * NH * VF;
        int h = gw / VF, k = gw % VF;
        const float* Wvc = branch ? Wvc1 : Wvc0;
        const float* Wvn = branch ? Wvn1 : Wvn0;
        const float* a   = branch ? a1 : a0;
        const float* wn = Wvn + ((size_t)h * VF + k) * FILT;
        const float* wc = Wvc + ((size_t)h * VF + k) * FILT;
        float v1 = wn[lane] * a[h * 128 + lane] + wn[lane + 32] * a[h * 128 + lane + 32];
        float v2 = wc[lane] * a[h * 128 + 64 + lane] + wc[lane + 32] * a[h * 128 + 96 + lane];
#pragma unroll
        for (int o = 16; o; o >>= 1) {
            v1 += __shfl_xor_sync(0xffffffffu, v1, o);
            v2 += __shfl_xor_sync(0xffffffffu, v2, o);
        }
        if (lane == 0) {
            g_w1[branch][h * VF + k] = v1;
            g_w2[branch][h * VF + k] = v2;
        }
    } else {
        int n = (bid - 288) * 256 + threadIdx.x;
        if (n >= N_NODES) return;
        int b = (is_int[n] == 1) ? 0 : 1;
        int pos = atomicAdd(&g_cnt[b], 1);
        g_perm[b][pos] = n;
        g_meta[n].x = (pos << 1) | b;
    }
}

// ---------------- fp16 mma.sync GEMM (m16n8k16) + fused s1/s2 -------------------
#define AS2 68
#define BS2 136
#define A_U32 (128 * AS2)
#define B_BUF_U32 (64 * BS2)
#define GSMEM_BYTES ((A_U32 + 2 * B_BUF_U32) * 4)

__global__ void __launch_bounds__(256, 2)
gemm_kernel(const float* __restrict__ v_int, const float* __restrict__ v_nh) {
    extern __shared__ uint32_t sm[];
    uint32_t* As = sm;
    uint32_t* Bs0 = sm + A_U32;

    const int branch = blockIdx.y;
    const int cnt = g_cnt[branch];
    const int bm = blockIdx.x * 128;
    if (bm >= cnt) return;

    const int tid = threadIdx.x;
    const int lane = tid & 31;
    const int wid = tid >> 5;
    const int g = lane >> 2;
    const int tg = lane & 3;
    const int warp_m = wid & 3;
    const int warp_n = wid >> 2;

    const uint32_t sbB = smem_u32(Bs0);

    {
        const int k2 = tid >> 2;
        const int coff = (tid & 3) * 32;
        const uint32_t* Bsrc = g_Bh[branch] + (size_t)k2 * NCOLS + coff;
        const uint32_t bdst = sbB + (uint32_t)(k2 * BS2 + coff) * 4u;
#pragma unroll
        for (int j = 0; j < 8; j++) cp_async16(bdst + j * 16, Bsrc + j * 4);
        CP_COMMIT();
#pragma unroll
        for (int j = 0; j < 8; j++)
            cp_async16(bdst + B_BUF_U32 * 4 + j * 16, Bsrc + 128 + j * 4);
        CP_COMMIT();
    }

    const int r_row = tid >> 1;
    const int grl = bm + r_row;
    const int nd = g_perm[branch][grl < cnt ? grl : cnt - 1];
    {
        const int ch2 = (tid & 1) * 32;
        const float4* Ag = (const float4*)((branch ? v_nh : v_int) +
                                           (size_t)nd * VF + ch2 * 2);
        uint2* dst = (uint2*)(As + r_row * AS2 + ch2);
#pragma unroll
        for (int j = 0; j < 16; j++) {
            float4 v = Ag[j];
            dst[j] = make_uint2(pack_f16x2(v.x, v.y), pack_f16x2(v.z, v.w));
        }
    }

#pragma unroll 1
    for (int s = 0; s < 3; s++) {
        if (s < 2) { CP_WAIT(1); } else { CP_WAIT(0); }
        __syncthreads();

        const uint32_t* Bs = Bs0 + (s & 1) * B_BUF_U32;

        float acc[2][8][4];
#pragma unroll
        for (int mt = 0; mt < 2; mt++)
#pragma unroll
            for (int nt = 0; nt < 8; nt++)
#pragma unroll
                for (int q = 0; q < 4; q++) acc[mt][nt][q] = 0.f;

        const int ar = warp_m * 32 + g;
        const int cb = warp_n * 64 + g;
#pragma unroll
        for (int k2_0 = 0; k2_0 < 64; k2_0 += 8) {
            uint32_t a[2][4];
#pragma unroll
            for (int mt = 0; mt < 2; mt++) {
                const uint32_t* ap = As + (ar + mt * 16) * AS2 + k2_0 + tg;
                a[mt][0] = ap[0];
                a[mt][1] = ap[8 * AS2];
                a[mt][2] = ap[4];
                a[mt][3] = ap[8 * AS2 + 4];
            }
            uint32_t b[8][2];
            const uint32_t* bp0 = Bs + (k2_0 + tg) * BS2 + cb;
            const uint32_t* bp1 = bp0 + 4 * BS2;
#pragma unroll
            for (int nt = 0; nt < 8; nt++) {
                b[nt][0] = bp0[nt * 8];
                b[nt][1] = bp1[nt * 8];
            }
#pragma unroll
            for (int mt = 0; mt < 2; mt++)
#pragma unroll
                for (int nt = 0; nt < 8; nt++)
                    mma_f16(acc[mt][nt], a[mt], b[nt]);
        }

        __syncthreads();

        if (s == 0) {
            const int k2 = tid >> 2;
            const int coff = (tid & 3) * 32;
            const uint32_t* Bsrc = g_Bh[branch] + (size_t)k2 * NCOLS + 256 + coff;
            const uint32_t bdst = sbB + (uint32_t)(k2 * BS2 + coff) * 4u;
#pragma unroll
            for (int j = 0; j < 8; j++) cp_async16(bdst + j * 16, Bsrc + j * 4);
            CP_COMMIT();
        }

        // ---- epilogue: both Zc (fp16) and Zn (bf16) are 16-bit packed ----
        const int cbase = s * 128 + warp_n * 64;
        const bool isZc = cbase < ZC;
        const int coff = isZc ? cbase : cbase - ZC;
        uint32_t* zb = isZc ? (uint32_t*)g_Zch[branch] : (uint32_t*)g_Znh[branch];
#pragma unroll
        for (int mt = 0; mt < 2; mt++) {
            const int r0 = warp_m * 32 + mt * 16 + g;
            const int gr0 = bm + r0, gr1 = gr0 + 8;
            uint32_t* row0 = zb + ((size_t)gr0 * ZC + coff) / 2 + tg;
            uint32_t* row1 = zb + ((size_t)gr1 * ZC + coff) / 2 + tg;
            const bool ok0 = gr0 < cnt, ok1 = gr1 < cnt;
#pragma unroll
            for (int nt = 0; nt < 8; nt++) {
                uint32_t p0 = isZc ? pack_f16x2(acc[mt][nt][0], acc[mt][nt][1])
                                   : pack_bf16x2(acc[mt][nt][0], acc[mt][nt][1]);
                uint32_t p1 = isZc ? pack_f16x2(acc[mt][nt][2], acc[mt][nt][3])
                                   : pack_bf16x2(acc[mt][nt][2], acc[mt][nt][3]);
                if (ok0) row0[nt * 4] = p0;
                if (ok1) row1[nt * 4] = p1;
            }
        }
    }

    // ---- fused s1/s2 from fp16 A tile ----
    float* wsv = (float*)Bs0;
    for (int i = tid; i < 6 * 128; i += 256) {
        int d = i >> 7, k = i & 127;
        wsv[d * 132 + k] = (d < 3) ? g_w1[branch][d * 128 + k]
                                   : g_w2[branch][(d - 3) * 128 + k];
    }
    __syncthreads();
    {
        const int dset = (tid & 1) * 3;
        const __half2* arow = (const __half2*)(As + r_row * AS2);
        const float* w0 = wsv + (dset + 0) * 132;
        const float* w1 = wsv + (dset + 1) * 132;
        const float* w2 = wsv + (dset + 2) * 132;
        float s0 = 0.f, s1 = 0.f, s2 = 0.f;
#pragma unroll 8
        for (int k2 = 0; k2 < 64; k2++) {
            float2 av = __half22float2(arow[k2]);
            s0 += av.x * w0[2 * k2] + av.y * w0[2 * k2 + 1];
            s1 += av.x * w1[2 * k2] + av.y * w1[2 * k2 + 1];
            s2 += av.x * w2[2 * k2] + av.y * w2[2 * k2 + 1];
        }
        if (grl < cnt) {
            if (tid & 1) {
                g_s2v[nd] = make_float4(s0, s1, s2,
                                        __int_as_float((grl << 1) | branch));
            } else {
                float* mp = (float*)&g_meta[nd];
                mp[1] = s0; mp[2] = s1; mp[3] = s2;
            }
        }
    }
}

// ---------------- weight kernel: one THREAD per (node, branch) -----------------
// Scattered g_meta loads batched in chunks of 5 (clamped indices, no branch
// around the LDG) for MLP.
__global__ __launch_bounds__(256)
void weight_kernel(const int* __restrict__ idx_int, const int* __restrict__ idx_nh,
                   const float* __restrict__ e_int, const float* __restrict__ e_nh) {
    const int branch = blockIdx.y;
    const int* __restrict__ idx   = branch ? idx_nh : idx_int;
    const float* __restrict__ edg = branch ? e_nh : e_int;

    int n = blockIdx.x * 256 + threadIdx.x;
    if (n >= N_NODES) return;

    int iv[KNBR];
    float ev[KNBR];
    const int2* ip = (const int2*)(idx + (size_t)n * KNBR);
    const float2* ep = (const float2*)(edg + (size_t)n * KNBR);
#pragma unroll
    for (int j = 0; j < 5; j++) {
        int2 a = ip[j];   iv[2 * j] = a.x; iv[2 * j + 1] = a.y;
        float2 b = ep[j]; ev[2 * j] = b.x; ev[2 * j + 1] = b.y;
    }

    float4 sv = g_s2v[n];
    const int pb = __float_as_int(sv.w);
    const bool nact = (pb & 1) == branch;
    const float s20 = nact ? sv.x : 0.f;
    const float s21 = nact ? sv.y : 0.f;
    const float s22 = nact ? sv.z : 0.f;

    uint4* rec = g_rec[branch] + (size_t)n * KNBR;
    float ps0 = 0.f, ps1 = 0.f, ps2 = 0.f;
    int cg = 0, nbcnt = 0;

#pragma unroll
    for (int c = 0; c < 2; c++) {
        int4 m[5];
        bool val[5];
#pragma unroll
        for (int j = 0; j < 5; j++) {            // unconditional clamped loads
            int i = iv[c * 5 + j];
            val[j] = (i >= 0);
            m[j] = g_meta[val[j] ? i : 0];
        }
#pragma unroll
        for (int j = 0; j < 5; j++) {
            int k = c * 5 + j;
            if (val[j]) {
                nbcnt++;
                bool gk = (m[j].x & 1) == branch;
                float s10 = gk ? __int_as_float(m[j].y) : 0.f;
                float s11 = gk ? __int_as_float(m[j].z) : 0.f;
                float s12 = gk ? __int_as_float(m[j].w) : 0.f;
                float p0 = __expf((s10 + s20) * ev[k]);
                float p1 = __expf((s11 + s21) * ev[k]);
                float p2 = __expf((s12 + s22) * ev[k]);
                ps0 += p0; ps1 += p1; ps2 += p2;
                if (gk) {
                    rec[cg] = make_uint4((uint32_t)((m[j].x >> 1) * (ZC * 2)),
                                         __float_as_uint(p0), __float_as_uint(p1),
                                         __float_as_uint(p2));
                    cg++;
                }
            } else {
                ps0 += 1.f; ps1 += 1.f; ps2 += 1.f;   // padded slot: exp(0)
            }
        }
    }

    float inv = 1.f / fmaxf((float)nbcnt, 1.f);
    g_hdr[branch][n] = make_float4(__fdividef(inv, ps0), __fdividef(inv, ps1),
                                   __fdividef(inv, ps2),
                                   __int_as_float(cg | (pb << 4)));
}

// ---------------- gather kernel: one warp per (node, branch) -------------------
// Two batched chunks of 5 predicated LDG.128s (MLP=5), normalizer folded into
// the staged weights.
__global__ __launch_bounds__(256)
void gather_kernel(const float* __restrict__ bv_int, const float* __restrict__ bv_nh,
                   float* __restrict__ out) {
    const int branch = blockIdx.y;
    const float* __restrict__ bv = branch ? bv_nh : bv_int;
    float* __restrict__ o = out + (size_t)branch * N_NODES * OUTC;

    __shared__ int   soff[8][12];
    __shared__ float swt[8][NH][12];

    const int wslot = threadIdx.x >> 5;
    const int lane = threadIdx.x & 31;
    const int n = (blockIdx.x * 256 + threadIdx.x) >> 5;
    if (n >= N_NODES) return;

    float4 hdr = g_hdr[branch][n];
    const int w = __float_as_int(hdr.w);
    const int cg = w & 15;
    const int pb = w >> 4;
    const bool nact = (pb & 1) == branch;
    const int pos_self = pb >> 1;

    if (lane < cg) {
        uint4 r = g_rec[branch][(size_t)n * KNBR + lane];
        soff[wslot][lane] = (int)r.x;
        swt[wslot][0][lane] = __uint_as_float(r.y) * hdr.x;  // fold normalizer
        swt[wslot][1][lane] = __uint_as_float(r.z) * hdr.y;
        swt[wslot][2][lane] = __uint_as_float(r.w) * hdr.z;
    }
    __syncwarp();

    const bool gl = lane < 24;
    const int myh = gl ? (lane >> 3) : 0;

    unsigned long long a01 = 0, a23 = 0, a45 = 0, a67 = 0;
    const char* __restrict__ Zb = (const char*)g_Znh[branch];
    const int lane16 = lane * 16;

#pragma unroll
    for (int c = 0; c < 2; c++) {
        const int base = c * 5;
        if (base < cg) {                          // warp-uniform
            uint4 v[5];
            float wk[5];
#pragma unroll
            for (int j = 0; j < 5; j++) {         // batched predicated loads
                if (gl && base + j < cg) {
                    v[j] = *(const uint4*)(Zb + soff[wslot][base + j] + lane16);
                    wk[j] = swt[wslot][myh][base + j];
                }
            }
#pragma unroll
            for (int j = 0; j < 5; j++) {
                if (gl && base + j < cg) {
                    unsigned long long wk2;
                    asm("mov.b64 %0, {%1, %1};" : "=l"(wk2) : "f"(wk[j]));
                    FMA2(a01, wk2, bf2_f32x2(v[j].x));
                    FMA2(a23, wk2, bf2_f32x2(v[j].y));
                    FMA2(a45, wk2, bf2_f32x2(v[j].z));
                    FMA2(a67, wk2, bf2_f32x2(v[j].w));
                }
            }
        }
    }

    if (gl) {
        float2 f01 = *(float2*)&a01;
        float2 f23 = *(float2*)&a23;
        float2 f45 = *(float2*)&a45;
        float2 f67 = *(float2*)&a67;
        float2 zc0 = make_float2(0.f, 0.f), zc1 = zc0, zc2 = zc0, zc3 = zc0;
        if (nact) {
            uint4 zc = *(const uint4*)(g_Zch[branch] + (size_t)pos_self * ZC + lane * 8);
            zc0 = __half22float2(*(__half2*)&zc.x);
            zc1 = __half22float2(*(__half2*)&zc.y);
            zc2 = __half22float2(*(__half2*)&zc.z);
            zc3 = __half22float2(*(__half2*)&zc.w);
        }
        const float4* bvp = (const float4*)(bv + lane * 8);
        float4 b0 = bvp[0], b1 = bvp[1];
        float4 o0, o1;
        o0.x = fmaxf(f01.x + zc0.x + b0.x, 0.f);
        o0.y = fmaxf(f01.y + zc0.y + b0.y, 0.f);
        o0.z = fmaxf(f23.x + zc1.x + b0.z, 0.f);
        o0.w = fmaxf(f23.y + zc1.y + b0.w, 0.f);
        o1.x = fmaxf(f45.x + zc2.x + b1.x, 0.f);
        o1.y = fmaxf(f45.y + zc2.y + b1.y, 0.f);
        o1.z = fmaxf(f67.x + zc3.x + b1.z, 0.f);
        o1.w = fmaxf(f67.y + zc3.y + b1.w, 0.f);
        float4* op = (float4*)(o + (size_t)n * OUTC + lane * 8);
        op[0] = o0;
        op[1] = o1;
    }
}

// ---------------- launch ---------------------------------------------------------
extern "C" void kernel_launch(void* const* d_in, const int* in_sizes, int n_in,
                              void* d_out, int out_size) {
    const float* vertices_int = (const float*)d_in[0];
    const float* vertices_nh  = (const float*)d_in[1];
    const int*   nh_indices   = (const int*)d_in[2];
    const int*   int_indices  = (const int*)d_in[3];
    const float* nh_edges     = (const float*)d_in[4];
    const float* int_edges    = (const float*)d_in[5];
    const int*   is_int       = (const int*)d_in[6];
    const float* Wvc_int      = (const float*)d_in[7];
    const float* Wvc_nh       = (const float*)d_in[8];
    const float* Wvn_int      = (const float*)d_in[9];
    const float* Wvn_nh       = (const float*)d_in[10];
    const float* bv_int       = (const float*)d_in[11];
    const float* bv_nh        = (const float*)d_in[12];
    const float* a_int        = (const float*)d_in[13];
    const float* a_nh         = (const float*)d_in[14];
    float* out = (float*)d_out;

    cudaFuncSetAttribute(gemm_kernel,
                         cudaFuncAttributeMaxDynamicSharedMemorySize, GSMEM_BYTES);

    reset_kernel<<<1, 32>>>();
    setup_kernel<<<288 + (N_NODES + 255) / 256, 256>>>(
        Wvc_int, Wvn_int, a_int, Wvc_nh, Wvn_nh, a_nh, is_int);

    dim3 gg((N_NODES + 127) / 128, 2);
    gemm_kernel<<<gg, 256, GSMEM_BYTES>>>(vertices_int, vertices_nh);

    dim3 wgrid((N_NODES + 255) / 256, 2);
    weight_kernel<<<wgrid, 256>>>(int_indices, nh_indices, int_edges, nh_edges);

    dim3 ggr((N_NODES * 32 + 255) / 256, 2);
    gather_kernel<<<ggr, 256>>>(bv_int, bv_nh, out);
}

// round 12
// speedup vs baseline: 1.0677x; 1.0677x over previous
#include <cuda_runtime.h>
#include <cuda_fp16.h>
#include <cuda_bf16.h>
#include <cstdint>

#define N_NODES 100000
#define VF      128
#define FILT    64
#define NH      3
#define KNBR    10
#define ZC      192
#define NCOLS   384
#define OUTC    192

// ---------------- scratch (static device globals) --------------------------
__device__ __half         g_Zch[2][(size_t)N_NODES * ZC];   // fp16, compacted
__device__ __nv_bfloat16  g_Znh[2][(size_t)N_NODES * ZC];   // bf16, compacted
__device__ uint32_t       g_Bh[2][(VF / 2) * NCOLS];        // fp16x2 packed [k2][c]
__device__ float          g_w1[2][NH * VF];
__device__ float          g_w2[2][NH * VF];
__device__ int4           g_meta[N_NODES];   // {(pos<<1)|b, s1h0, s1h1, s1h2}
__device__ float4         g_s2v[N_NODES];    // {s2h0, s2h1, s2h2, bits((pos<<1)|b)}
__device__ uint4          g_rec[2][(size_t)N_NODES * KNBR]; // {off, p0, p1, p2}
__device__ float4         g_hdr[2][N_NODES]; // {rs0, rs1, rs2, bits(cg|(pb<<4))}
__device__ int            g_perm[2][N_NODES];
__device__ int            g_cnt[2];

// ---------------- helpers ----------------------------------------------------
__device__ __forceinline__ void mma_f16(float (&d)[4], const uint32_t (&a)[4],
                                        const uint32_t (&b)[2]) {
    asm volatile(
        "mma.sync.aligned.m16n8k16.row.col.f32.f16.f16.f32 "
        "{%0,%1,%2,%3}, {%4,%5,%6,%7}, {%8,%9}, {%0,%1,%2,%3};"
        : "+f"(d[0]), "+f"(d[1]), "+f"(d[2]), "+f"(d[3])
        : "r"(a[0]), "r"(a[1]), "r"(a[2]), "r"(a[3]), "r"(b[0]), "r"(b[1]));
}
__device__ __forceinline__ uint32_t smem_u32(const void* p) {
    uint32_t a;
    asm("{ .reg .u64 t; cvta.to.shared.u64 t, %1; cvt.u32.u64 %0, t; }"
        : "=r"(a) : "l"(p));
    return a;
}
__device__ __forceinline__ void cp_async16(uint32_t saddr, const void* g) {
    asm volatile("cp.async.cg.shared.global [%0], [%1], 16;"
                 :: "r"(saddr), "l"(g) : "memory");
}
#define CP_COMMIT() asm volatile("cp.async.commit_group;" ::: "memory")
#define CP_WAIT(n)  asm volatile("cp.async.wait_group %0;" :: "n"(n) : "memory")
__device__ __forceinline__ uint32_t pack_bf16x2(float lo, float hi) {
    uint32_t r;
    asm("cvt.rn.bf16x2.f32 %0, %1, %2;" : "=r"(r) : "f"(hi), "f"(lo));
    return r;
}
__device__ __forceinline__ uint32_t pack_f16x2(float lo, float hi) {
    __half2 h = __floats2half2_rn(lo, hi);
    return *(uint32_t*)&h;
}
// bf16x2 -> packed f32x2 (low elem in low word)
__device__ __forceinline__ unsigned long long bf2_f32x2(uint32_t u) {
    unsigned long long r;
    uint32_t lo = u << 16;
    uint32_t hi = u & 0xffff0000u;
    asm("mov.b64 %0, {%1, %2};" : "=l"(r) : "r"(lo), "r"(hi));
    return r;
}
#define FMA2(acc, a, b) \
    asm("fma.rn.f32x2 %0, %1, %2, %0;" : "+l"(acc) : "l"(a), "l"(b))

// ---------------- reset -------------------------------------------------------
__global__ void reset_kernel() {
    if (threadIdx.x == 0) { g_cnt[0] = 0; g_cnt[1] = 0; }
}

// ---------------- fused setup: prepack | wvec | compact -------------------------
__global__ void setup_kernel(const float* __restrict__ Wvc0, const float* __restrict__ Wvn0,
                             const float* __restrict__ a0,
                             const float* __restrict__ Wvc1, const float* __restrict__ Wvn1,
                             const float* __restrict__ a1,
                             const int* __restrict__ is_int) {
    const int bid = blockIdx.x;
    if (bid < 192) {
        const int branch = bid >= 96;
        const float* Wvc = branch ? Wvc1 : Wvc0;
        const float* Wvn = branch ? Wvn1 : Wvn0;
        int i = (bid - branch * 96) * 256 + threadIdx.x;     // < 24576
        int k2 = i / NCOLS, c = i % NCOLS;
        const float* W;
        int h, o;
        if (c < ZC) { W = Wvc; h = c / FILT; o = c % FILT; }
        else        { W = Wvn; h = (c - ZC) / FILT; o = (c - ZC) % FILT; }
        float v0 = W[((size_t)h * VF + 2 * k2) * FILT + o];
        float v1 = W[((size_t)h * VF + 2 * k2 + 1) * FILT + o];
        g_Bh[branch][i] = pack_f16x2(v0, v1);
    } else if (bid < 288) {
        int w = (bid - 192) * 8 + (threadIdx.x >> 5);        // < 768
        int lane = threadIdx.x & 31;
        const int branch = w >= NH * VF;
        int gw = w - branch * NH * VF;
        int h = gw / VF, k = gw % VF;
        const float* Wvc = branch ? Wvc1 : Wvc0;
        const float* Wvn = branch ? Wvn1 : Wvn0;
        const float* a   = branch ? a1 : a0;
        const float* wn = Wvn + ((size_t)h * VF + k) * FILT;
        const float* wc = Wvc + ((size_t)h * VF + k) * FILT;
        float v1 = wn[lane] * a[h * 128 + lane] + wn[lane + 32] * a[h * 128 + lane + 32];
        float v2 = wc[lane] * a[h * 128 + 64 + lane] + wc[lane + 32] * a[h * 128 + 96 + lane];
#pragma unroll
        for (int o = 16; o; o >>= 1) {
            v1 += __shfl_xor_sync(0xffffffffu, v1, o);
            v2 += __shfl_xor_sync(0xffffffffu, v2, o);
        }
        if (lane == 0) {
            g_w1[branch][h * VF + k] = v1;
            g_w2[branch][h * VF + k] = v2;
        }
    } else {
        int n = (bid - 288) * 256 + threadIdx.x;
        if (n >= N_NODES) return;
        int b = (is_int[n] == 1) ? 0 : 1;
        int pos = atomicAdd(&g_cnt[b], 1);
        g_perm[b][pos] = n;
        g_meta[n].x = (pos << 1) | b;
    }
}

// ---------------- fp16 mma.sync GEMM (m16n8k16) + fused s1/s2 -------------------
#define AS2 68
#define BS2 136
#define A_U32 (128 * AS2)
#define B_BUF_U32 (64 * BS2)
#define GSMEM_BYTES ((A_U32 + 2 * B_BUF_U32) * 4)

__global__ void __launch_bounds__(256, 2)
gemm_kernel(const float* __restrict__ v_int, const float* __restrict__ v_nh) {
    extern __shared__ uint32_t sm[];
    uint32_t* As = sm;
    uint32_t* Bs0 = sm + A_U32;

    const int branch = blockIdx.y;
    const int cnt = g_cnt[branch];
    const int bm = blockIdx.x * 128;
    if (bm >= cnt) return;

    const int tid = threadIdx.x;
    const int lane = tid & 31;
    const int wid = tid >> 5;
    const int g = lane >> 2;
    const int tg = lane & 3;
    const int warp_m = wid & 3;
    const int warp_n = wid >> 2;

    const uint32_t sbB = smem_u32(Bs0);

    {
        const int k2 = tid >> 2;
        const int coff = (tid & 3) * 32;
        const uint32_t* Bsrc = g_Bh[branch] + (size_t)k2 * NCOLS + coff;
        const uint32_t bdst = sbB + (uint32_t)(k2 * BS2 + coff) * 4u;
#pragma unroll
        for (int j = 0; j < 8; j++) cp_async16(bdst + j * 16, Bsrc + j * 4);
        CP_COMMIT();
#pragma unroll
        for (int j = 0; j < 8; j++)
            cp_async16(bdst + B_BUF_U32 * 4 + j * 16, Bsrc + 128 + j * 4);
        CP_COMMIT();
    }

    const int r_row = tid >> 1;
    const int grl = bm + r_row;
    const int nd = g_perm[branch][grl < cnt ? grl : cnt - 1];
    {
        const int ch2 = (tid & 1) * 32;
        const float4* Ag = (const float4*)((branch ? v_nh : v_int) +
                                           (size_t)nd * VF + ch2 * 2);
        uint2* dst = (uint2*)(As + r_row * AS2 + ch2);
#pragma unroll
        for (int j = 0; j < 16; j++) {
            float4 v = Ag[j];
            dst[j] = make_uint2(pack_f16x2(v.x, v.y), pack_f16x2(v.z, v.w));
        }
    }

#pragma unroll 1
    for (int s = 0; s < 3; s++) {
        if (s < 2) { CP_WAIT(1); } else { CP_WAIT(0); }
        __syncthreads();

        const uint32_t* Bs = Bs0 + (s & 1) * B_BUF_U32;

        float acc[2][8][4];
#pragma unroll
        for (int mt = 0; mt < 2; mt++)
#pragma unroll
            for (int nt = 0; nt < 8; nt++)
#pragma unroll
                for (int q = 0; q < 4; q++) acc[mt][nt][q] = 0.f;

        const int ar = warp_m * 32 + g;
        const int cb = warp_n * 64 + g;
#pragma unroll
        for (int k2_0 = 0; k2_0 < 64; k2_0 += 8) {
            uint32_t a[2][4];
#pragma unroll
            for (int mt = 0; mt < 2; mt++) {
                const uint32_t* ap = As + (ar + mt * 16) * AS2 + k2_0 + tg;
                a[mt][0] = ap[0];
                a[mt][1] = ap[8 * AS2];
                a[mt][2] = ap[4];
                a[mt][3] = ap[8 * AS2 + 4];
            }
            uint32_t b[8][2];
            const uint32_t* bp0 = Bs + (k2_0 + tg) * BS2 + cb;
            const uint32_t* bp1 = bp0 + 4 * BS2;
#pragma unroll
            for (int nt = 0; nt < 8; nt++) {
                b[nt][0] = bp0[nt * 8];
                b[nt][1] = bp1[nt * 8];
            }
#pragma unroll
            for (int mt = 0; mt < 2; mt++)
#pragma unroll
                for (int nt = 0; nt < 8; nt++)
                    mma_f16(acc[mt][nt], a[mt], b[nt]);
        }

        __syncthreads();

        if (s == 0) {
            const int k2 = tid >> 2;
            const int coff = (tid & 3) * 32;
            const uint32_t* Bsrc = g_Bh[branch] + (size_t)k2 * NCOLS + 256 + coff;
            const uint32_t bdst = sbB + (uint32_t)(k2 * BS2 + coff) * 4u;
#pragma unroll
            for (int j = 0; j < 8; j++) cp_async16(bdst + j * 16, Bsrc + j * 4);
            CP_COMMIT();
        }

        // ---- epilogue: both Zc (fp16) and Zn (bf16) are 16-bit packed ----
        const int cbase = s * 128 + warp_n * 64;
        const bool isZc = cbase < ZC;
        const int coff = isZc ? cbase : cbase - ZC;
        uint32_t* zb = isZc ? (uint32_t*)g_Zch[branch] : (uint32_t*)g_Znh[branch];
#pragma unroll
        for (int mt = 0; mt < 2; mt++) {
            const int r0 = warp_m * 32 + mt * 16 + g;
            const int gr0 = bm + r0, gr1 = gr0 + 8;
            uint32_t* row0 = zb + ((size_t)gr0 * ZC + coff) / 2 + tg;
            uint32_t* row1 = zb + ((size_t)gr1 * ZC + coff) / 2 + tg;
            const bool ok0 = gr0 < cnt, ok1 = gr1 < cnt;
#pragma unroll
            for (int nt = 0; nt < 8; nt++) {
                uint32_t p0 = isZc ? pack_f16x2(acc[mt][nt][0], acc[mt][nt][1])
                                   : pack_bf16x2(acc[mt][nt][0], acc[mt][nt][1]);
                uint32_t p1 = isZc ? pack_f16x2(acc[mt][nt][2], acc[mt][nt][3])
                                   : pack_bf16x2(acc[mt][nt][2], acc[mt][nt][3]);
                if (ok0) row0[nt * 4] = p0;
                if (ok1) row1[nt * 4] = p1;
            }
        }
    }

    // ---- fused s1/s2 from fp16 A tile ----
    float* wsv = (float*)Bs0;
    for (int i = tid; i < 6 * 128; i += 256) {
        int d = i >> 7, k = i & 127;
        wsv[d * 132 + k] = (d < 3) ? g_w1[branch][d * 128 + k]
                                   : g_w2[branch][(d - 3) * 128 + k];
    }
    __syncthreads();
    {
        const int dset = (tid & 1) * 3;
        const __half2* arow = (const __half2*)(As + r_row * AS2);
        const float* w0 = wsv + (dset + 0) * 132;
        const float* w1 = wsv + (dset + 1) * 132;
        const float* w2 = wsv + (dset + 2) * 132;
        float s0 = 0.f, s1 = 0.f, s2 = 0.f;
#pragma unroll 8
        for (int k2 = 0; k2 < 64; k2++) {
            float2 av = __half22float2(arow[k2]);
            s0 += av.x * w0[2 * k2] + av.y * w0[2 * k2 + 1];
            s1 += av.x * w1[2 * k2] + av.y * w1[2 * k2 + 1];
            s2 += av.x * w2[2 * k2] + av.y * w2[2 * k2 + 1];
        }
        if (grl < cnt) {
            if (tid & 1) {
                g_s2v[nd] = make_float4(s0, s1, s2,
                                        __int_as_float((grl << 1) | branch));
            } else {
                float* mp = (float*)&g_meta[nd];
                mp[1] = s0; mp[2] = s1; mp[3] = s2;
            }
        }
    }
}

// ---------------- weight kernel: one THREAD per (node, branch) -----------------
// Scattered g_meta loads batched in chunks of 5 (clamped indices, no branch
// around the LDG) for MLP. (R11 version — verified 17.8us)
__global__ __launch_bounds__(256)
void weight_kernel(const int* __restrict__ idx_int, const int* __restrict__ idx_nh,
                   const float* __restrict__ e_int, const float* __restrict__ e_nh) {
    const int branch = blockIdx.y;
    const int* __restrict__ idx   = branch ? idx_nh : idx_int;
    const float* __restrict__ edg = branch ? e_nh : e_int;

    int n = blockIdx.x * 256 + threadIdx.x;
    if (n >= N_NODES) return;

    int iv[KNBR];
    float ev[KNBR];
    const int2* ip = (const int2*)(idx + (size_t)n * KNBR);
    const float2* ep = (const float2*)(edg + (size_t)n * KNBR);
#pragma unroll
    for (int j = 0; j < 5; j++) {
        int2 a = ip[j];   iv[2 * j] = a.x; iv[2 * j + 1] = a.y;
        float2 b = ep[j]; ev[2 * j] = b.x; ev[2 * j + 1] = b.y;
    }

    float4 sv = g_s2v[n];
    const int pb = __float_as_int(sv.w);
    const bool nact = (pb & 1) == branch;
    const float s20 = nact ? sv.x : 0.f;
    const float s21 = nact ? sv.y : 0.f;
    const float s22 = nact ? sv.z : 0.f;

    uint4* rec = g_rec[branch] + (size_t)n * KNBR;
    float ps0 = 0.f, ps1 = 0.f, ps2 = 0.f;
    int cg = 0, nbcnt = 0;

#pragma unroll
    for (int c = 0; c < 2; c++) {
        int4 m[5];
        bool val[5];
#pragma unroll
        for (int j = 0; j < 5; j++) {            // unconditional clamped loads
            int i = iv[c * 5 + j];
            val[j] = (i >= 0);
            m[j] = g_meta[val[j] ? i : 0];
        }
#pragma unroll
        for (int j = 0; j < 5; j++) {
            int k = c * 5 + j;
            if (val[j]) {
                nbcnt++;
                bool gk = (m[j].x & 1) == branch;
                float s10 = gk ? __int_as_float(m[j].y) : 0.f;
                float s11 = gk ? __int_as_float(m[j].z) : 0.f;
                float s12 = gk ? __int_as_float(m[j].w) : 0.f;
                float p0 = __expf((s10 + s20) * ev[k]);
                float p1 = __expf((s11 + s21) * ev[k]);
                float p2 = __expf((s12 + s22) * ev[k]);
                ps0 += p0; ps1 += p1; ps2 += p2;
                if (gk) {
                    rec[cg] = make_uint4((uint32_t)((m[j].x >> 1) * (ZC * 2)),
                                         __float_as_uint(p0), __float_as_uint(p1),
                                         __float_as_uint(p2));
                    cg++;
                }
            } else {
                ps0 += 1.f; ps1 += 1.f; ps2 += 1.f;   // padded slot: exp(0)
            }
        }
    }

    float inv = 1.f / fmaxf((float)nbcnt, 1.f);
    g_hdr[branch][n] = make_float4(__fdividef(inv, ps0), __fdividef(inv, ps1),
                                   __fdividef(inv, ps2),
                                   __int_as_float(cg | (pb << 4)));
}

// ---------------- gather kernel: one warp per (node, branch) -------------------
// R10 form (simple dependent loop — verified fast); normalizer folded into the
// staged smem weights.
__global__ __launch_bounds__(256)
void gather_kernel(const float* __restrict__ bv_int, const float* __restrict__ bv_nh,
                   float* __restrict__ out) {
    const int branch = blockIdx.y;
    const float* __restrict__ bv = branch ? bv_nh : bv_int;
    float* __restrict__ o = out + (size_t)branch * N_NODES * OUTC;

    __shared__ int   soff[8][12];
    __shared__ float swt[8][NH][12];

    const int wslot = threadIdx.x >> 5;
    const int lane = threadIdx.x & 31;
    const int n = (blockIdx.x * 256 + threadIdx.x) >> 5;
    if (n >= N_NODES) return;

    float4 hdr = g_hdr[branch][n];
    const int w = __float_as_int(hdr.w);
    const int cg = w & 15;
    const int pb = w >> 4;
    const bool nact = (pb & 1) == branch;
    const int pos_self = pb >> 1;

    if (lane < cg) {
        uint4 r = g_rec[branch][(size_t)n * KNBR + lane];
        soff[wslot][lane] = (int)r.x;
        swt[wslot][0][lane] = __uint_as_float(r.y) * hdr.x;  // fold normalizer
        swt[wslot][1][lane] = __uint_as_float(r.z) * hdr.y;
        swt[wslot][2][lane] = __uint_as_float(r.w) * hdr.z;
    }
    __syncwarp();

    const bool gl = lane < 24;
    const int myh = gl ? (lane >> 3) : 0;

    unsigned long long a01 = 0, a23 = 0, a45 = 0, a67 = 0;
    const char* __restrict__ Zb = (const char*)g_Znh[branch];
    const int lane16 = lane * 16;
    for (int k = 0; k < cg; k++) {
        if (gl) {
            int off = soff[wslot][k];
            float wk = swt[wslot][myh][k];
            unsigned long long wk2;
            asm("mov.b64 %0, {%1, %1};" : "=l"(wk2) : "f"(wk));
            uint4 v = *(const uint4*)(Zb + off + lane16);
            FMA2(a01, wk2, bf2_f32x2(v.x));
            FMA2(a23, wk2, bf2_f32x2(v.y));
            FMA2(a45, wk2, bf2_f32x2(v.z));
            FMA2(a67, wk2, bf2_f32x2(v.w));
        }
    }

    if (gl) {
        float2 f01 = *(float2*)&a01;
        float2 f23 = *(float2*)&a23;
        float2 f45 = *(float2*)&a45;
        float2 f67 = *(float2*)&a67;
        float2 zc0 = make_float2(0.f, 0.f), zc1 = zc0, zc2 = zc0, zc3 = zc0;
        if (nact) {
            uint4 zc = *(const uint4*)(g_Zch[branch] + (size_t)pos_self * ZC + lane * 8);
            zc0 = __half22float2(*(__half2*)&zc.x);
            zc1 = __half22float2(*(__half2*)&zc.y);
            zc2 = __half22float2(*(__half2*)&zc.z);
            zc3 = __half22float2(*(__half2*)&zc.w);
        }
        const float4* bvp = (const float4*)(bv + lane * 8);
        float4 b0 = bvp[0], b1 = bvp[1];
        float4 o0, o1;
        o0.x = fmaxf(f01.x + zc0.x + b0.x, 0.f);
        o0.y = fmaxf(f01.y + zc0.y + b0.y, 0.f);
        o0.z = fmaxf(f23.x + zc1.x + b0.z, 0.f);
        o0.w = fmaxf(f23.y + zc1.y + b0.w, 0.f);
        o1.x = fmaxf(f45.x + zc2.x + b1.x, 0.f);
        o1.y = fmaxf(f45.y + zc2.y + b1.y, 0.f);
        o1.z = fmaxf(f67.x + zc3.x + b1.z, 0.f);
        o1.w = fmaxf(f67.y + zc3.y + b1.w, 0.f);
        float4* op = (float4*)(o + (size_t)n * OUTC + lane * 8);
        op[0] = o0;
        op[1] = o1;
    }
}

// ---------------- launch ---------------------------------------------------------
extern "C" void kernel_launch(void* const* d_in, const int* in_sizes, int n_in,
                              void* d_out, int out_size) {
    const float* vertices_int = (const float*)d_in[0];
    const float* vertices_nh  = (const float*)d_in[1];
    const int*   nh_indices   = (const int*)d_in[2];
    const int*   int_indices  = (const int*)d_in[3];
    const float* nh_edges     = (const float*)d_in[4];
    const float* int_edges    = (const float*)d_in[5];
    const int*   is_int       = (const int*)d_in[6];
    const float* Wvc_int      = (const float*)d_in[7];
    const float* Wvc_nh       = (const float*)d_in[8];
    const float* Wvn_int      = (const float*)d_in[9];
    const float* Wvn_nh       = (const float*)d_in[10];
    const float* bv_int       = (const float*)d_in[11];
    const float* bv_nh        = (const float*)d_in[12];
    const float* a_int        = (const float*)d_in[13];
    const float* a_nh         = (const float*)d_in[14];
    float* out = (float*)d_out;

    cudaFuncSetAttribute(gemm_kernel,
                         cudaFuncAttributeMaxDynamicSharedMemorySize, GSMEM_BYTES);

    reset_kernel<<<1, 32>>>();
    setup_kernel<<<288 + (N_NODES + 255) / 256, 256>>>(
        Wvc_int, Wvn_int, a_int, Wvc_nh, Wvn_nh, a_nh, is_int);

    dim3 gg((N_NODES + 127) / 128, 2);
    gemm_kernel<<<gg, 256, GSMEM_BYTES>>>(vertices_int, vertices_nh);

    dim3 wgrid((N_NODES + 255) / 256, 2);
    weight_kernel<<<wgrid, 256>>>(int_indices, nh_indices, int_edges, nh_edges);

    dim3 ggr((N_NODES * 32 + 255) / 256, 2);
    gather_kernel<<<ggr, 256>>>(bv_int, bv_nh, out);
}

// round 13
// speedup vs baseline: 1.0765x; 1.0082x over previous
#include <cuda_runtime.h>
#include <cuda_fp16.h>
#include <cuda_bf16.h>
#include <cstdint>

#define N_NODES 100000
#define VF      128
#define FILT    64
#define NH      3
#define KNBR    10
#define ZC      192
#define NCOLS   384
#define OUTC    192

// ---------------- scratch (static device globals) --------------------------
__device__ __half         g_Zch[2][(size_t)N_NODES * ZC];   // fp16, compacted
__device__ __nv_bfloat16  g_Znh[2][(size_t)N_NODES * ZC];   // bf16, compacted
__device__ uint32_t       g_Bh[2][(VF / 2) * NCOLS];        // fp16x2 packed [k2][c]
__device__ float          g_w1[2][NH * VF];
__device__ float          g_w2[2][NH * VF];
__device__ int4           g_meta[N_NODES];   // {(pos<<1)|b, s1h0, s1h1, s1h2}
__device__ float4         g_s2v[N_NODES];    // {s2h0, s2h1, s2h2, bits((pos<<1)|b)}
__device__ uint4          g_rec[2][(size_t)N_NODES * KNBR]; // {off, p0, p1, p2}
__device__ float4         g_hdr[2][N_NODES]; // {rs0, rs1, rs2, bits(cg|(pb<<4))}
__device__ int            g_perm[2][N_NODES];
__device__ int            g_cnt[2];          // zero-init; re-zeroed at graph tail

// ---------------- helpers ----------------------------------------------------
__device__ __forceinline__ void mma_f16(float (&d)[4], const uint32_t (&a)[4],
                                        const uint32_t (&b)[2]) {
    asm volatile(
        "mma.sync.aligned.m16n8k16.row.col.f32.f16.f16.f32 "
        "{%0,%1,%2,%3}, {%4,%5,%6,%7}, {%8,%9}, {%0,%1,%2,%3};"
        : "+f"(d[0]), "+f"(d[1]), "+f"(d[2]), "+f"(d[3])
        : "r"(a[0]), "r"(a[1]), "r"(a[2]), "r"(a[3]), "r"(b[0]), "r"(b[1]));
}
__device__ __forceinline__ uint32_t smem_u32(const void* p) {
    uint32_t a;
    asm("{ .reg .u64 t; cvta.to.shared.u64 t, %1; cvt.u32.u64 %0, t; }"
        : "=r"(a) : "l"(p));
    return a;
}
__device__ __forceinline__ void cp_async16(uint32_t saddr, const void* g) {
    asm volatile("cp.async.cg.shared.global [%0], [%1], 16;"
                 :: "r"(saddr), "l"(g) : "memory");
}
#define CP_COMMIT() asm volatile("cp.async.commit_group;" ::: "memory")
#define CP_WAIT(n)  asm volatile("cp.async.wait_group %0;" :: "n"(n) : "memory")
__device__ __forceinline__ uint32_t pack_bf16x2(float lo, float hi) {
    uint32_t r;
    asm("cvt.rn.bf16x2.f32 %0, %1, %2;" : "=r"(r) : "f"(hi), "f"(lo));
    return r;
}
__device__ __forceinline__ uint32_t pack_f16x2(float lo, float hi) {
    __half2 h = __floats2half2_rn(lo, hi);
    return *(uint32_t*)&h;
}
// bf16x2 -> packed f32x2 (low elem in low word)
__device__ __forceinline__ unsigned long long bf2_f32x2(uint32_t u) {
    unsigned long long r;
    uint32_t lo = u << 16;
    uint32_t hi = u & 0xffff0000u;
    asm("mov.b64 %0, {%1, %2};" : "=l"(r) : "r"(lo), "r"(hi));
    return r;
}
#define FMA2(acc, a, b) \
    asm("fma.rn.f32x2 %0, %1, %2, %0;" : "+l"(acc) : "l"(a), "l"(b))

// ---------------- fused setup: prepack | wvec | compact -------------------------
__global__ void setup_kernel(const float* __restrict__ Wvc0, const float* __restrict__ Wvn0,
                             const float* __restrict__ a0,
                             const float* __restrict__ Wvc1, const float* __restrict__ Wvn1,
                             const float* __restrict__ a1,
                             const int* __restrict__ is_int) {
    const int bid = blockIdx.x;
    if (bid < 192) {
        const int branch = bid >= 96;
        const float* Wvc = branch ? Wvc1 : Wvc0;
        const float* Wvn = branch ? Wvn1 : Wvn0;
        int i = (bid - branch * 96) * 256 + threadIdx.x;     // < 24576
        int k2 = i / NCOLS, c = i % NCOLS;
        const float* W;
        int h, o;
        if (c < ZC) { W = Wvc; h = c / FILT; o = c % FILT; }
        else        { W = Wvn; h = (c - ZC) / FILT; o = (c - ZC) % FILT; }
        float v0 = W[((size_t)h * VF + 2 * k2) * FILT + o];
        float v1 = W[((size_t)h * VF + 2 * k2 + 1) * FILT + o];
        g_Bh[branch][i] = pack_f16x2(v0, v1);
    } else if (bid < 288) {
        int w = (bid - 192) * 8 + (threadIdx.x >> 5);        // < 768
        int lane = threadIdx.x & 31;
        const int branch = w >= NH * VF;
        int gw = w - branch * NH * VF;
        int h = gw / VF, k = gw % VF;
        const float* Wvc = branch ? Wvc1 : Wvc0;
        const float* Wvn = branch ? Wvn1 : Wvn0;
        const float* a   = branch ? a1 : a0;
        const float* wn = Wvn + ((size_t)h * VF + k) * FILT;
        const float* wc = Wvc + ((size_t)h * VF + k) * FILT;
        float v1 = wn[lane] * a[h * 128 + lane] + wn[lane + 32] * a[h * 128 + lane + 32];
        float v2 = wc[lane] * a[h * 128 + 64 + lane] + wc[lane + 32] * a[h * 128 + 96 + lane];
#pragma unroll
        for (int o = 16; o; o >>= 1) {
            v1 += __shfl_xor_sync(0xffffffffu, v1, o);
            v2 += __shfl_xor_sync(0xffffffffu, v2, o);
        }
        if (lane == 0) {
            g_w1[branch][h * VF + k] = v1;
            g_w2[branch][h * VF + k] = v2;
        }
    } else {
        int n = (bid - 288) * 256 + threadIdx.x;
        if (n >= N_NODES) return;
        int b = (is_int[n] == 1) ? 0 : 1;
        int pos = atomicAdd(&g_cnt[b], 1);
        g_perm[b][pos] = n;
        g_meta[n].x = (pos << 1) | b;
    }
}

// ---------------- fp16 mma.sync GEMM (m16n8k16) + fused s1/s2 -------------------
// Concatenated grid: blocks [0, nb0) handle branch 0, [nb0, nb0+nb1) branch 1.
#define AS2 68
#define BS2 136
#define A_U32 (128 * AS2)
#define B_BUF_U32 (64 * BS2)
#define GSMEM_BYTES ((A_U32 + 2 * B_BUF_U32) * 4)
#define GEMM_GRID 784

__global__ void __launch_bounds__(256, 2)
gemm_kernel(const float* __restrict__ v_int, const float* __restrict__ v_nh) {
    extern __shared__ uint32_t sm[];
    uint32_t* As = sm;
    uint32_t* Bs0 = sm + A_U32;

    const int cnt0 = g_cnt[0];
    const int nb0 = (cnt0 + 127) >> 7;
    int branch, bm, cnt;
    if ((int)blockIdx.x < nb0) {
        branch = 0; bm = blockIdx.x * 128; cnt = cnt0;
    } else {
        branch = 1; bm = (blockIdx.x - nb0) * 128; cnt = g_cnt[1];
        if (bm >= cnt) return;
    }

    const int tid = threadIdx.x;
    const int lane = tid & 31;
    const int g = lane >> 2;
    const int tg = lane & 3;
    const int wid = tid >> 5;
    const int warp_m = wid & 3;
    const int warp_n = wid >> 2;

    const uint32_t sbB = smem_u32(Bs0);

    {
        const int k2 = tid >> 2;
        const int coff = (tid & 3) * 32;
        const uint32_t* Bsrc = g_Bh[branch] + (size_t)k2 * NCOLS + coff;
        const uint32_t bdst = sbB + (uint32_t)(k2 * BS2 + coff) * 4u;
#pragma unroll
        for (int j = 0; j < 8; j++) cp_async16(bdst + j * 16, Bsrc + j * 4);
        CP_COMMIT();
#pragma unroll
        for (int j = 0; j < 8; j++)
            cp_async16(bdst + B_BUF_U32 * 4 + j * 16, Bsrc + 128 + j * 4);
        CP_COMMIT();
    }

    const int r_row = tid >> 1;
    const int grl = bm + r_row;
    const int nd = g_perm[branch][grl < cnt ? grl : cnt - 1];
    {
        const int ch2 = (tid & 1) * 32;
        const float4* Ag = (const float4*)((branch ? v_nh : v_int) +
                                           (size_t)nd * VF + ch2 * 2);
        uint2* dst = (uint2*)(As + r_row * AS2 + ch2);
#pragma unroll
        for (int j = 0; j < 16; j++) {
            float4 v = Ag[j];
            dst[j] = make_uint2(pack_f16x2(v.x, v.y), pack_f16x2(v.z, v.w));
        }
    }

#pragma unroll 1
    for (int s = 0; s < 3; s++) {
        if (s < 2) { CP_WAIT(1); } else { CP_WAIT(0); }
        __syncthreads();

        const uint32_t* Bs = Bs0 + (s & 1) * B_BUF_U32;

        float acc[2][8][4];
#pragma unroll
        for (int mt = 0; mt < 2; mt++)
#pragma unroll
            for (int nt = 0; nt < 8; nt++)
#pragma unroll
                for (int q = 0; q < 4; q++) acc[mt][nt][q] = 0.f;

        const int ar = warp_m * 32 + g;
        const int cb = warp_n * 64 + g;
#pragma unroll
        for (int k2_0 = 0; k2_0 < 64; k2_0 += 8) {
            uint32_t a[2][4];
#pragma unroll
            for (int mt = 0; mt < 2; mt++) {
                const uint32_t* ap = As + (ar + mt * 16) * AS2 + k2_0 + tg;
                a[mt][0] = ap[0];
                a[mt][1] = ap[8 * AS2];
                a[mt][2] = ap[4];
                a[mt][3] = ap[8 * AS2 + 4];
            }
            uint32_t b[8][2];
            const uint32_t* bp0 = Bs + (k2_0 + tg) * BS2 + cb;
            const uint32_t* bp1 = bp0 + 4 * BS2;
#pragma unroll
            for (int nt = 0; nt < 8; nt++) {
                b[nt][0] = bp0[nt * 8];
                b[nt][1] = bp1[nt * 8];
            }
#pragma unroll
            for (int mt = 0; mt < 2; mt++)
#pragma unroll
                for (int nt = 0; nt < 8; nt++)
                    mma_f16(acc[mt][nt], a[mt], b[nt]);
        }

        __syncthreads();

        if (s == 0) {
            const int k2 = tid >> 2;
            const int coff = (tid & 3) * 32;
            const uint32_t* Bsrc = g_Bh[branch] + (size_t)k2 * NCOLS + 256 + coff;
            const uint32_t bdst = sbB + (uint32_t)(k2 * BS2 + coff) * 4u;
#pragma unroll
            for (int j = 0; j < 8; j++) cp_async16(bdst + j * 16, Bsrc + j * 4);
            CP_COMMIT();
        }

        // ---- epilogue: both Zc (fp16) and Zn (bf16) are 16-bit packed ----
        const int cbase = s * 128 + warp_n * 64;
        const bool isZc = cbase < ZC;
        const int coff = isZc ? cbase : cbase - ZC;
        uint32_t* zb = isZc ? (uint32_t*)g_Zch[branch] : (uint32_t*)g_Znh[branch];
#pragma unroll
        for (int mt = 0; mt < 2; mt++) {
            const int r0 = warp_m * 32 + mt * 16 + g;
            const int gr0 = bm + r0, gr1 = gr0 + 8;
            uint32_t* row0 = zb + ((size_t)gr0 * ZC + coff) / 2 + tg;
            uint32_t* row1 = zb + ((size_t)gr1 * ZC + coff) / 2 + tg;
            const bool ok0 = gr0 < cnt, ok1 = gr1 < cnt;
#pragma unroll
            for (int nt = 0; nt < 8; nt++) {
                uint32_t p0 = isZc ? pack_f16x2(acc[mt][nt][0], acc[mt][nt][1])
                                   : pack_bf16x2(acc[mt][nt][0], acc[mt][nt][1]);
                uint32_t p1 = isZc ? pack_f16x2(acc[mt][nt][2], acc[mt][nt][3])
                                   : pack_bf16x2(acc[mt][nt][2], acc[mt][nt][3]);
                if (ok0) row0[nt * 4] = p0;
                if (ok1) row1[nt * 4] = p1;
            }
        }
    }

    // ---- fused s1/s2 from fp16 A tile ----
    float* wsv = (float*)Bs0;
    for (int i = tid; i < 6 * 128; i += 256) {
        int d = i >> 7, k = i & 127;
        wsv[d * 132 + k] = (d < 3) ? g_w1[branch][d * 128 + k]
                                   : g_w2[branch][(d - 3) * 128 + k];
    }
    __syncthreads();
    {
        const int dset = (tid & 1) * 3;
        const __half2* arow = (const __half2*)(As + r_row * AS2);
        const float* w0 = wsv + (dset + 0) * 132;
        const float* w1 = wsv + (dset + 1) * 132;
        const float* w2 = wsv + (dset + 2) * 132;
        float s0 = 0.f, s1 = 0.f, s2 = 0.f;
#pragma unroll 8
        for (int k2 = 0; k2 < 64; k2++) {
            float2 av = __half22float2(arow[k2]);
            s0 += av.x * w0[2 * k2] + av.y * w0[2 * k2 + 1];
            s1 += av.x * w1[2 * k2] + av.y * w1[2 * k2 + 1];
            s2 += av.x * w2[2 * k2] + av.y * w2[2 * k2 + 1];
        }
        if (grl < cnt) {
            if (tid & 1) {
                g_s2v[nd] = make_float4(s0, s1, s2,
                                        __int_as_float((grl << 1) | branch));
            } else {
                float* mp = (float*)&g_meta[nd];
                mp[1] = s0; mp[2] = s1; mp[3] = s2;
            }
        }
    }
}

// ---------------- weight kernel: one THREAD per (node, branch) -----------------
__global__ __launch_bounds__(256)
void weight_kernel(const int* __restrict__ idx_int, const int* __restrict__ idx_nh,
                   const float* __restrict__ e_int, const float* __restrict__ e_nh) {
    const int branch = blockIdx.y;
    const int* __restrict__ idx   = branch ? idx_nh : idx_int;
    const float* __restrict__ edg = branch ? e_nh : e_int;

    int n = blockIdx.x * 256 + threadIdx.x;
    if (n >= N_NODES) return;

    int iv[KNBR];
    float ev[KNBR];
    const int2* ip = (const int2*)(idx + (size_t)n * KNBR);
    const float2* ep = (const float2*)(edg + (size_t)n * KNBR);
#pragma unroll
    for (int j = 0; j < 5; j++) {
        int2 a = ip[j];   iv[2 * j] = a.x; iv[2 * j + 1] = a.y;
        float2 b = ep[j]; ev[2 * j] = b.x; ev[2 * j + 1] = b.y;
    }

    float4 sv = g_s2v[n];
    const int pb = __float_as_int(sv.w);
    const bool nact = (pb & 1) == branch;
    const float s20 = nact ? sv.x : 0.f;
    const float s21 = nact ? sv.y : 0.f;
    const float s22 = nact ? sv.z : 0.f;

    uint4* rec = g_rec[branch] + (size_t)n * KNBR;
    float ps0 = 0.f, ps1 = 0.f, ps2 = 0.f;
    int cg = 0, nbcnt = 0;

#pragma unroll
    for (int c = 0; c < 2; c++) {
        int4 m[5];
        bool val[5];
#pragma unroll
        for (int j = 0; j < 5; j++) {            // unconditional clamped loads
            int i = iv[c * 5 + j];
            val[j] = (i >= 0);
            m[j] = g_meta[val[j] ? i : 0];
        }
#pragma unroll
        for (int j = 0; j < 5; j++) {
            int k = c * 5 + j;
            if (val[j]) {
                nbcnt++;
                bool gk = (m[j].x & 1) == branch;
                float s10 = gk ? __int_as_float(m[j].y) : 0.f;
                float s11 = gk ? __int_as_float(m[j].z) : 0.f;
                float s12 = gk ? __int_as_float(m[j].w) : 0.f;
                float p0 = __expf((s10 + s20) * ev[k]);
                float p1 = __expf((s11 + s21) * ev[k]);
                float p2 = __expf((s12 + s22) * ev[k]);
                ps0 += p0; ps1 += p1; ps2 += p2;
                if (gk) {
                    rec[cg] = make_uint4((uint32_t)((m[j].x >> 1) * (ZC * 2)),
                                         __float_as_uint(p0), __float_as_uint(p1),
                                         __float_as_uint(p2));
                    cg++;
                }
            } else {
                ps0 += 1.f; ps1 += 1.f; ps2 += 1.f;   // padded slot: exp(0)
            }
        }
    }

    float inv = 1.f / fmaxf((float)nbcnt, 1.f);
    g_hdr[branch][n] = make_float4(__fdividef(inv, ps0), __fdividef(inv, ps1),
                                   __fdividef(inv, ps2),
                                   __int_as_float(cg | (pb << 4)));
}

// ---------------- gather kernel: one warp per (node, branch) -------------------
// 2-stage software pipeline over the dependent gather loop (MLP=2).
// Also re-zeroes g_cnt at graph tail for the next replay.
__global__ __launch_bounds__(256)
void gather_kernel(const float* __restrict__ bv_int, const float* __restrict__ bv_nh,
                   float* __restrict__ out) {
    const int branch = blockIdx.y;
    const float* __restrict__ bv = branch ? bv_nh : bv_int;
    float* __restrict__ o = out + (size_t)branch * N_NODES * OUTC;

    if (blockIdx.x == 0 && blockIdx.y == 0 && threadIdx.x == 0) {
        g_cnt[0] = 0;   // reset for next graph replay (unused by weight/gather)
        g_cnt[1] = 0;
    }

    __shared__ int   soff[8][12];
    __shared__ float swt[8][NH][12];

    const int wslot = threadIdx.x >> 5;
    const int lane = threadIdx.x & 31;
    const int n = (blockIdx.x * 256 + threadIdx.x) >> 5;
    if (n >= N_NODES) return;

    float4 hdr = g_hdr[branch][n];
    const int w = __float_as_int(hdr.w);
    const int cg = w & 15;
    const int pb = w >> 4;
    const bool nact = (pb & 1) == branch;
    const int pos_self = pb >> 1;

    if (lane < cg) {
        uint4 r = g_rec[branch][(size_t)n * KNBR + lane];
        soff[wslot][lane] = (int)r.x;
        swt[wslot][0][lane] = __uint_as_float(r.y) * hdr.x;  // fold normalizer
        swt[wslot][1][lane] = __uint_as_float(r.z) * hdr.y;
        swt[wslot][2][lane] = __uint_as_float(r.w) * hdr.z;
    }
    __syncwarp();

    const bool gl = lane < 24;
    const int myh = gl ? (lane >> 3) : 0;

    unsigned long long a01 = 0, a23 = 0, a45 = 0, a67 = 0;
    const char* __restrict__ Zb = (const char*)g_Znh[branch];
    const int lane16 = lane * 16;

    // 2-stage pipeline: v/wk hold iteration k, vn/wn prefetch k+1
    uint4 v = make_uint4(0, 0, 0, 0);
    float wk = 0.f;
    if (cg > 0 && gl) {
        v = *(const uint4*)(Zb + soff[wslot][0] + lane16);
        wk = swt[wslot][myh][0];
    }
#pragma unroll 1
    for (int k = 1; k < cg; k++) {
        uint4 vn = make_uint4(0, 0, 0, 0);
        float wn = 0.f;
        if (gl) {
            vn = *(const uint4*)(Zb + soff[wslot][k] + lane16);
            wn = swt[wslot][myh][k];
        }
        if (gl) {
            unsigned long long wk2;
            asm("mov.b64 %0, {%1, %1};" : "=l"(wk2) : "f"(wk));
            FMA2(a01, wk2, bf2_f32x2(v.x));
            FMA2(a23, wk2, bf2_f32x2(v.y));
            FMA2(a45, wk2, bf2_f32x2(v.z));
            FMA2(a67, wk2, bf2_f32x2(v.w));
        }
        v = vn;
        wk = wn;
    }
    if (cg > 0 && gl) {
        unsigned long long wk2;
        asm("mov.b64 %0, {%1, %1};" : "=l"(wk2) : "f"(wk));
        FMA2(a01, wk2, bf2_f32x2(v.x));
        FMA2(a23, wk2, bf2_f32x2(v.y));
        FMA2(a45, wk2, bf2_f32x2(v.z));
        FMA2(a67, wk2, bf2_f32x2(v.w));
    }

    if (gl) {
        float2 f01 = *(float2*)&a01;
        float2 f23 = *(float2*)&a23;
        float2 f45 = *(float2*)&a45;
        float2 f67 = *(float2*)&a67;
        float2 zc0 = make_float2(0.f, 0.f), zc1 = zc0, zc2 = zc0, zc3 = zc0;
        if (nact) {
            uint4 zc = *(const uint4*)(g_Zch[branch] + (size_t)pos_self * ZC + lane * 8);
            zc0 = __half22float2(*(__half2*)&zc.x);
            zc1 = __half22float2(*(__half2*)&zc.y);
            zc2 = __half22float2(*(__half2*)&zc.z);
            zc3 = __half22float2(*(__half2*)&zc.w);
        }
        const float4* bvp = (const float4*)(bv + lane * 8);
        float4 b0 = bvp[0], b1 = bvp[1];
        float4 o0, o1;
        o0.x = fmaxf(f01.x + zc0.x + b0.x, 0.f);
        o0.y = fmaxf(f01.y + zc0.y + b0.y, 0.f);
        o0.z = fmaxf(f23.x + zc1.x + b0.z, 0.f);
        o0.w = fmaxf(f23.y + zc1.y + b0.w, 0.f);
        o1.x = fmaxf(f45.x + zc2.x + b1.x, 0.f);
        o1.y = fmaxf(f45.y + zc2.y + b1.y, 0.f);
        o1.z = fmaxf(f67.x + zc3.x + b1.z, 0.f);
        o1.w = fmaxf(f67.y + zc3.y + b1.w, 0.f);
        float4* op = (float4*)(o + (size_t)n * OUTC + lane * 8);
        op[0] = o0;
        op[1] = o1;
    }
}

// ---------------- launch ---------------------------------------------------------
extern "C" void kernel_launch(void* const* d_in, const int* in_sizes, int n_in,
                              void* d_out, int out_size) {
    const float* vertices_int = (const float*)d_in[0];
    const float* vertices_nh  = (const float*)d_in[1];
    const int*   nh_indices   = (const int*)d_in[2];
    const int*   int_indices  = (const int*)d_in[3];
    const float* nh_edges     = (const float*)d_in[4];
    const float* int_edges    = (const float*)d_in[5];
    const int*   is_int       = (const int*)d_in[6];
    const float* Wvc_int      = (const float*)d_in[7];
    const float* Wvc_nh       = (const float*)d_in[8];
    const float* Wvn_int      = (const float*)d_in[9];
    const float* Wvn_nh       = (const float*)d_in[10];
    const float* bv_int       = (const float*)d_in[11];
    const float* bv_nh        = (const float*)d_in[12];
    const float* a_int        = (const float*)d_in[13];
    const float* a_nh         = (const float*)d_in[14];
    float* out = (float*)d_out;

    cudaFuncSetAttribute(gemm_kernel,
                         cudaFuncAttributeMaxDynamicSharedMemorySize, GSMEM_BYTES);

    setup_kernel<<<288 + (N_NODES + 255) / 256, 256>>>(
        Wvc_int, Wvn_int, a_int, Wvc_nh, Wvn_nh, a_nh, is_int);

    gemm_kernel<<<GEMM_GRID, 256, GSMEM_BYTES>>>(vertices_int, vertices_nh);

    dim3 wgrid((N_NODES + 255) / 256, 2);
    weight_kernel<<<wgrid, 256>>>(int_indices, nh_indices, int_edges, nh_edges);

    dim3 ggr((N_NODES * 32 + 255) / 256, 2);
    gather_kernel<<<ggr, 256>>>(bv_int, bv_nh, out);
}

// round 14
// speedup vs baseline: 1.2590x; 1.1696x over previous
#include <cuda_runtime.h>
#include <cuda_fp16.h>
#include <cuda_bf16.h>
#include <cstdint>

#define N_NODES 100000
#define VF      128
#define FILT    64
#define NH      3
#define KNBR    10
#define ZC      192
#define NCOLS   384
#define OUTC    192

// ---------------- scratch (static device globals) --------------------------
__device__ __half         g_Zch[2][(size_t)N_NODES * ZC];   // fp16, compacted
__device__ __nv_bfloat16  g_Znh[2][(size_t)N_NODES * ZC];   // bf16, compacted
__device__ uint32_t       g_Bh[2][(VF / 2) * NCOLS];        // fp16x2 packed [k2][c]
__device__ float          g_w1[2][NH * VF];
__device__ float          g_w2[2][NH * VF];
__device__ int4           g_meta[N_NODES];   // {(pos<<1)|b, s1h0, s1h1, s1h2}
__device__ float4         g_s2v[N_NODES];    // {s2h0, s2h1, s2h2, bits((pos<<1)|b)}
__device__ uint4          g_rec[2][(size_t)N_NODES * KNBR]; // {off, p0, p1, p2}
__device__ float4         g_hdr[2][N_NODES]; // {rs0, rs1, rs2, bits(cg|(pb<<4))}
__device__ int            g_perm[2][N_NODES];
__device__ int            g_cnt[2];          // zero-init; re-zeroed at graph tail

// ---------------- helpers ----------------------------------------------------
__device__ __forceinline__ void mma_f16(float (&d)[4], const uint32_t (&a)[4],
                                        const uint32_t (&b)[2]) {
    asm volatile(
        "mma.sync.aligned.m16n8k16.row.col.f32.f16.f16.f32 "
        "{%0,%1,%2,%3}, {%4,%5,%6,%7}, {%8,%9}, {%0,%1,%2,%3};"
        : "+f"(d[0]), "+f"(d[1]), "+f"(d[2]), "+f"(d[3])
        : "r"(a[0]), "r"(a[1]), "r"(a[2]), "r"(a[3]), "r"(b[0]), "r"(b[1]));
}
__device__ __forceinline__ uint32_t smem_u32(const void* p) {
    uint32_t a;
    asm("{ .reg .u64 t; cvta.to.shared.u64 t, %1; cvt.u32.u64 %0, t; }"
        : "=r"(a) : "l"(p));
    return a;
}
__device__ __forceinline__ void cp_async16(uint32_t saddr, const void* g) {
    asm volatile("cp.async.cg.shared.global [%0], [%1], 16;"
                 :: "r"(saddr), "l"(g) : "memory");
}
#define CP_COMMIT() asm volatile("cp.async.commit_group;" ::: "memory")
#define CP_WAIT(n)  asm volatile("cp.async.wait_group %0;" :: "n"(n) : "memory")
__device__ __forceinline__ uint32_t pack_bf16x2(float lo, float hi) {
    uint32_t r;
    asm("cvt.rn.bf16x2.f32 %0, %1, %2;" : "=r"(r) : "f"(hi), "f"(lo));
    return r;
}
__device__ __forceinline__ uint32_t pack_f16x2(float lo, float hi) {
    __half2 h = __floats2half2_rn(lo, hi);
    return *(uint32_t*)&h;
}
// bf16x2 -> packed f32x2 (low elem in low word)
__device__ __forceinline__ unsigned long long bf2_f32x2(uint32_t u) {
    unsigned long long r;
    uint32_t lo = u << 16;
    uint32_t hi = u & 0xffff0000u;
    asm("mov.b64 %0, {%1, %2};" : "=l"(r) : "r"(lo), "r"(hi));
    return r;
}
#define FMA2(acc, a, b) \
    asm("fma.rn.f32x2 %0, %1, %2, %0;" : "+l"(acc) : "l"(a), "l"(b))

// ---------------- fused setup: prepack | wvec | compact -------------------------
__global__ void setup_kernel(const float* __restrict__ Wvc0, const float* __restrict__ Wvn0,
                             const float* __restrict__ a0,
                             const float* __restrict__ Wvc1, const float* __restrict__ Wvn1,
                             const float* __restrict__ a1,
                             const int* __restrict__ is_int) {
    const int bid = blockIdx.x;
    if (bid < 192) {
        const int branch = bid >= 96;
        const float* Wvc = branch ? Wvc1 : Wvc0;
        const float* Wvn = branch ? Wvn1 : Wvn0;
        int i = (bid - branch * 96) * 256 + threadIdx.x;     // < 24576
        int k2 = i / NCOLS, c = i % NCOLS;
        const float* W;
        int h, o;
        if (c < ZC) { W = Wvc; h = c / FILT; o = c % FILT; }
        else        { W = Wvn; h = (c - ZC) / FILT; o = (c - ZC) % FILT; }
        float v0 = W[((size_t)h * VF + 2 * k2) * FILT + o];
        float v1 = W[((size_t)h * VF + 2 * k2 + 1) * FILT + o];
        g_Bh[branch][i] = pack_f16x2(v0, v1);
    } else if (bid < 288) {
        int w = (bid - 192) * 8 + (threadIdx.x >> 5);        // < 768
        int lane = threadIdx.x & 31;
        const int branch = w >= NH * VF;
        int gw = w - branch * NH * VF;
        int h = gw / VF, k = gw % VF;
        const float* Wvc = branch ? Wvc1 : Wvc0;
        const float* Wvn = branch ? Wvn1 : Wvn0;
        const float* a   = branch ? a1 : a0;
        const float* wn = Wvn + ((size_t)h * VF + k) * FILT;
        const float* wc = Wvc + ((size_t)h * VF + k) * FILT;
        float v1 = wn[lane] * a[h * 128 + lane] + wn[lane + 32] * a[h * 128 + lane + 32];
        float v2 = wc[lane] * a[h * 128 + 64 + lane] + wc[lane + 32] * a[h * 128 + 96 + lane];
#pragma unroll
        for (int o = 16; o; o >>= 1) {
            v1 += __shfl_xor_sync(0xffffffffu, v1, o);
            v2 += __shfl_xor_sync(0xffffffffu, v2, o);
        }
        if (lane == 0) {
            g_w1[branch][h * VF + k] = v1;
            g_w2[branch][h * VF + k] = v2;
        }
    } else {
        // ---- warp-aggregated compaction: 2 atomics per warp, popc ranks ----
        int n = (bid - 288) * 256 + threadIdx.x;
        const int lane = threadIdx.x & 31;
        const bool valid = n < N_NODES;
        int b = -1;
        if (valid) b = (is_int[n] == 1) ? 0 : 1;
        uint32_t m0 = __ballot_sync(0xffffffffu, b == 0);
        uint32_t m1 = __ballot_sync(0xffffffffu, b == 1);
        int base0 = 0, base1 = 0;
        if (lane == 0) {
            base0 = atomicAdd(&g_cnt[0], __popc(m0));
            base1 = atomicAdd(&g_cnt[1], __popc(m1));
        }
        base0 = __shfl_sync(0xffffffffu, base0, 0);
        base1 = __shfl_sync(0xffffffffu, base1, 0);
        if (valid) {
            uint32_t below = (1u << lane) - 1u;
            int pos = (b == 0) ? base0 + __popc(m0 & below)
                               : base1 + __popc(m1 & below);
            g_perm[b][pos] = n;
            g_meta[n].x = (pos << 1) | b;
        }
    }
}

// ---------------- fp16 mma.sync GEMM (m16n8k16) + fused s1/s2 -------------------
// Concatenated grid: blocks [0, nb0) handle branch 0, rest branch 1.
#define AS2 68
#define BS2 136
#define A_U32 (128 * AS2)
#define B_BUF_U32 (64 * BS2)
#define GSMEM_BYTES ((A_U32 + 2 * B_BUF_U32) * 4)
#define GEMM_GRID 784

__global__ void __launch_bounds__(256, 2)
gemm_kernel(const float* __restrict__ v_int, const float* __restrict__ v_nh) {
    extern __shared__ uint32_t sm[];
    uint32_t* As = sm;
    uint32_t* Bs0 = sm + A_U32;

    const int cnt0 = g_cnt[0];
    const int nb0 = (cnt0 + 127) >> 7;
    int branch, bm, cnt;
    if ((int)blockIdx.x < nb0) {
        branch = 0; bm = blockIdx.x * 128; cnt = cnt0;
    } else {
        branch = 1; bm = (blockIdx.x - nb0) * 128; cnt = g_cnt[1];
        if (bm >= cnt) return;
    }

    const int tid = threadIdx.x;
    const int lane = tid & 31;
    const int g = lane >> 2;
    const int tg = lane & 3;
    const int wid = tid >> 5;
    const int warp_m = wid & 3;
    const int warp_n = wid >> 2;

    const uint32_t sbB = smem_u32(Bs0);

    {
        const int k2 = tid >> 2;
        const int coff = (tid & 3) * 32;
        const uint32_t* Bsrc = g_Bh[branch] + (size_t)k2 * NCOLS + coff;
        const uint32_t bdst = sbB + (uint32_t)(k2 * BS2 + coff) * 4u;
#pragma unroll
        for (int j = 0; j < 8; j++) cp_async16(bdst + j * 16, Bsrc + j * 4);
        CP_COMMIT();
#pragma unroll
        for (int j = 0; j < 8; j++)
            cp_async16(bdst + B_BUF_U32 * 4 + j * 16, Bsrc + 128 + j * 4);
        CP_COMMIT();
    }

    const int r_row = tid >> 1;
    const int grl = bm + r_row;
    const int nd = g_perm[branch][grl < cnt ? grl : cnt - 1];
    {
        const int ch2 = (tid & 1) * 32;
        const float4* Ag = (const float4*)((branch ? v_nh : v_int) +
                                           (size_t)nd * VF + ch2 * 2);
        uint2* dst = (uint2*)(As + r_row * AS2 + ch2);
#pragma unroll
        for (int j = 0; j < 16; j++) {
            float4 v = Ag[j];
            dst[j] = make_uint2(pack_f16x2(v.x, v.y), pack_f16x2(v.z, v.w));
        }
    }

#pragma unroll 1
    for (int s = 0; s < 3; s++) {
        if (s < 2) { CP_WAIT(1); } else { CP_WAIT(0); }
        __syncthreads();

        const uint32_t* Bs = Bs0 + (s & 1) * B_BUF_U32;

        float acc[2][8][4];
#pragma unroll
        for (int mt = 0; mt < 2; mt++)
#pragma unroll
            for (int nt = 0; nt < 8; nt++)
#pragma unroll
                for (int q = 0; q < 4; q++) acc[mt][nt][q] = 0.f;

        const int ar = warp_m * 32 + g;
        const int cb = warp_n * 64 + g;
#pragma unroll
        for (int k2_0 = 0; k2_0 < 64; k2_0 += 8) {
            uint32_t a[2][4];
#pragma unroll
            for (int mt = 0; mt < 2; mt++) {
                const uint32_t* ap = As + (ar + mt * 16) * AS2 + k2_0 + tg;
                a[mt][0] = ap[0];
                a[mt][1] = ap[8 * AS2];
                a[mt][2] = ap[4];
                a[mt][3] = ap[8 * AS2 + 4];
            }
            uint32_t b[8][2];
            const uint32_t* bp0 = Bs + (k2_0 + tg) * BS2 + cb;
            const uint32_t* bp1 = bp0 + 4 * BS2;
#pragma unroll
            for (int nt = 0; nt < 8; nt++) {
                b[nt][0] = bp0[nt * 8];
                b[nt][1] = bp1[nt * 8];
            }
#pragma unroll
            for (int mt = 0; mt < 2; mt++)
#pragma unroll
                for (int nt = 0; nt < 8; nt++)
                    mma_f16(acc[mt][nt], a[mt], b[nt]);
        }

        __syncthreads();

        if (s == 0) {
            const int k2 = tid >> 2;
            const int coff = (tid & 3) * 32;
            const uint32_t* Bsrc = g_Bh[branch] + (size_t)k2 * NCOLS + 256 + coff;
            const uint32_t bdst = sbB + (uint32_t)(k2 * BS2 + coff) * 4u;
#pragma unroll
            for (int j = 0; j < 8; j++) cp_async16(bdst + j * 16, Bsrc + j * 4);
            CP_COMMIT();
        }

        // ---- epilogue: both Zc (fp16) and Zn (bf16) are 16-bit packed ----
        const int cbase = s * 128 + warp_n * 64;
        const bool isZc = cbase < ZC;
        const int coff = isZc ? cbase : cbase - ZC;
        uint32_t* zb = isZc ? (uint32_t*)g_Zch[branch] : (uint32_t*)g_Znh[branch];
#pragma unroll
        for (int mt = 0; mt < 2; mt++) {
            const int r0 = warp_m * 32 + mt * 16 + g;
            const int gr0 = bm + r0, gr1 = gr0 + 8;
            uint32_t* row0 = zb + ((size_t)gr0 * ZC + coff) / 2 + tg;
            uint32_t* row1 = zb + ((size_t)gr1 * ZC + coff) / 2 + tg;
            const bool ok0 = gr0 < cnt, ok1 = gr1 < cnt;
#pragma unroll
            for (int nt = 0; nt < 8; nt++) {
                uint32_t p0 = isZc ? pack_f16x2(acc[mt][nt][0], acc[mt][nt][1])
                                   : pack_bf16x2(acc[mt][nt][0], acc[mt][nt][1]);
                uint32_t p1 = isZc ? pack_f16x2(acc[mt][nt][2], acc[mt][nt][3])
                                   : pack_bf16x2(acc[mt][nt][2], acc[mt][nt][3]);
                if (ok0) row0[nt * 4] = p0;
                if (ok1) row1[nt * 4] = p1;
            }
        }
    }

    // ---- fused s1/s2 from fp16 A tile ----
    float* wsv = (float*)Bs0;
    for (int i = tid; i < 6 * 128; i += 256) {
        int d = i >> 7, k = i & 127;
        wsv[d * 132 + k] = (d < 3) ? g_w1[branch][d * 128 + k]
                                   : g_w2[branch][(d - 3) * 128 + k];
    }
    __syncthreads();
    {
        const int dset = (tid & 1) * 3;
        const __half2* arow = (const __half2*)(As + r_row * AS2);
        const float* w0 = wsv + (dset + 0) * 132;
        const float* w1 = wsv + (dset + 1) * 132;
        const float* w2 = wsv + (dset + 2) * 132;
        float s0 = 0.f, s1 = 0.f, s2 = 0.f;
#pragma unroll 8
        for (int k2 = 0; k2 < 64; k2++) {
            float2 av = __half22float2(arow[k2]);
            s0 += av.x * w0[2 * k2] + av.y * w0[2 * k2 + 1];
            s1 += av.x * w1[2 * k2] + av.y * w1[2 * k2 + 1];
            s2 += av.x * w2[2 * k2] + av.y * w2[2 * k2 + 1];
        }
        if (grl < cnt) {
            if (tid & 1) {
                g_s2v[nd] = make_float4(s0, s1, s2,
                                        __int_as_float((grl << 1) | branch));
            } else {
                float* mp = (float*)&g_meta[nd];
                mp[1] = s0; mp[2] = s1; mp[3] = s2;
            }
        }
    }
}

// ---------------- weight kernel: one THREAD per (node, branch) -----------------
__global__ __launch_bounds__(256)
void weight_kernel(const int* __restrict__ idx_int, const int* __restrict__ idx_nh,
                   const float* __restrict__ e_int, const float* __restrict__ e_nh) {
    const int branch = blockIdx.y;
    const int* __restrict__ idx   = branch ? idx_nh : idx_int;
    const float* __restrict__ edg = branch ? e_nh : e_int;

    int n = blockIdx.x * 256 + threadIdx.x;
    if (n >= N_NODES) return;

    int iv[KNBR];
    float ev[KNBR];
    const int2* ip = (const int2*)(idx + (size_t)n * KNBR);
    const float2* ep = (const float2*)(edg + (size_t)n * KNBR);
#pragma unroll
    for (int j = 0; j < 5; j++) {
        int2 a = ip[j];   iv[2 * j] = a.x; iv[2 * j + 1] = a.y;
        float2 b = ep[j]; ev[2 * j] = b.x; ev[2 * j + 1] = b.y;
    }

    float4 sv = g_s2v[n];
    const int pb = __float_as_int(sv.w);
    const bool nact = (pb & 1) == branch;
    const float s20 = nact ? sv.x : 0.f;
    const float s21 = nact ? sv.y : 0.f;
    const float s22 = nact ? sv.z : 0.f;

    uint4* rec = g_rec[branch] + (size_t)n * KNBR;
    float ps0 = 0.f, ps1 = 0.f, ps2 = 0.f;
    int cg = 0, nbcnt = 0;

#pragma unroll
    for (int c = 0; c < 2; c++) {
        int4 m[5];
        bool val[5];
#pragma unroll
        for (int j = 0; j < 5; j++) {            // unconditional clamped loads
            int i = iv[c * 5 + j];
            val[j] = (i >= 0);
            m[j] = g_meta[val[j] ? i : 0];
        }
#pragma unroll
        for (int j = 0; j < 5; j++) {
            int k = c * 5 + j;
            if (val[j]) {
                nbcnt++;
                bool gk = (m[j].x & 1) == branch;
                float s10 = gk ? __int_as_float(m[j].y) : 0.f;
                float s11 = gk ? __int_as_float(m[j].z) : 0.f;
                float s12 = gk ? __int_as_float(m[j].w) : 0.f;
                float p0 = __expf((s10 + s20) * ev[k]);
                float p1 = __expf((s11 + s21) * ev[k]);
                float p2 = __expf((s12 + s22) * ev[k]);
                ps0 += p0; ps1 += p1; ps2 += p2;
                if (gk) {
                    rec[cg] = make_uint4((uint32_t)((m[j].x >> 1) * (ZC * 2)),
                                         __float_as_uint(p0), __float_as_uint(p1),
                                         __float_as_uint(p2));
                    cg++;
                }
            } else {
                ps0 += 1.f; ps1 += 1.f; ps2 += 1.f;   // padded slot: exp(0)
            }
        }
    }

    float inv = 1.f / fmaxf((float)nbcnt, 1.f);
    g_hdr[branch][n] = make_float4(__fdividef(inv, ps0), __fdividef(inv, ps1),
                                   __fdividef(inv, ps2),
                                   __int_as_float(cg | (pb << 4)));
}

// ---------------- gather kernel: flat (node, channel-group) mapping ------------
// 240 threads / 10 nodes per block; thread = (node j = tid/24, ch = tid%24).
// No idle lanes in the gather loop. Also re-zeroes g_cnt at graph tail.
#define GB_NODES 10
#define GB_THREADS 240

__global__ __launch_bounds__(GB_THREADS)
void gather_kernel(const float* __restrict__ bv_int, const float* __restrict__ bv_nh,
                   float* __restrict__ out) {
    const int branch = blockIdx.y;
    const float* __restrict__ bv = branch ? bv_nh : bv_int;
    float* __restrict__ o = out + (size_t)branch * N_NODES * OUTC;

    if (blockIdx.x == 0 && blockIdx.y == 0 && threadIdx.x == 0) {
        g_cnt[0] = 0;   // reset for next graph replay
        g_cnt[1] = 0;
    }

    __shared__ int   soff[GB_NODES][KNBR];
    __shared__ float swt[GB_NODES][NH][KNBR];
    __shared__ float srs[GB_NODES][NH];
    __shared__ int   scg[GB_NODES];
    __shared__ int   spb[GB_NODES];

    const int tid = threadIdx.x;
    const int n0 = blockIdx.x * GB_NODES;

    // stage headers
    if (tid < GB_NODES) {
        float4 hdr = g_hdr[branch][n0 + tid];
        int w = __float_as_int(hdr.w);
        scg[tid] = w & 15;
        spb[tid] = w >> 4;
        srs[tid][0] = hdr.x;
        srs[tid][1] = hdr.y;
        srs[tid][2] = hdr.z;
    }
    __syncthreads();

    // stage records (normalizer folded in)
    if (tid < GB_NODES * KNBR) {
        int j = tid / KNBR, s = tid % KNBR;
        if (s < scg[j]) {
            uint4 r = g_rec[branch][(size_t)(n0 + j) * KNBR + s];
            soff[j][s] = (int)r.x;
            swt[j][0][s] = __uint_as_float(r.y) * srs[j][0];
            swt[j][1][s] = __uint_as_float(r.z) * srs[j][1];
            swt[j][2][s] = __uint_as_float(r.w) * srs[j][2];
        }
    }
    __syncthreads();

    // gather: every thread active
    const int j = tid / 24;
    const int ch = tid - j * 24;
    const int myh = ch >> 3;
    const int cg = scg[j];

    unsigned long long a01 = 0, a23 = 0, a45 = 0, a67 = 0;
    const char* __restrict__ Zb = (const char*)g_Znh[branch];
    const int ch16 = ch * 16;
#pragma unroll 1
    for (int k = 0; k < cg; k++) {
        int off = soff[j][k];
        float wk = swt[j][myh][k];
        unsigned long long wk2;
        asm("mov.b64 %0, {%1, %1};" : "=l"(wk2) : "f"(wk));
        uint4 v = *(const uint4*)(Zb + off + ch16);
        FMA2(a01, wk2, bf2_f32x2(v.x));
        FMA2(a23, wk2, bf2_f32x2(v.y));
        FMA2(a45, wk2, bf2_f32x2(v.z));
        FMA2(a67, wk2, bf2_f32x2(v.w));
    }

    {
        const int pb = spb[j];
        const bool nact = (pb & 1) == branch;
        const int pos_self = pb >> 1;
        float2 f01 = *(float2*)&a01;
        float2 f23 = *(float2*)&a23;
        float2 f45 = *(float2*)&a45;
        float2 f67 = *(float2*)&a67;
        float2 zc0 = make_float2(0.f, 0.f), zc1 = zc0, zc2 = zc0, zc3 = zc0;
        if (nact) {
            uint4 zc = *(const uint4*)(g_Zch[branch] + (size_t)pos_self * ZC + ch * 8);
            zc0 = __half22float2(*(__half2*)&zc.x);
            zc1 = __half22float2(*(__half2*)&zc.y);
            zc2 = __half22float2(*(__half2*)&zc.z);
            zc3 = __half22float2(*(__half2*)&zc.w);
        }
        const float4* bvp = (const float4*)(bv + ch * 8);
        float4 b0 = bvp[0], b1 = bvp[1];
        float4 o0, o1;
        o0.x = fmaxf(f01.x + zc0.x + b0.x, 0.f);
        o0.y = fmaxf(f01.y + zc0.y + b0.y, 0.f);
        o0.z = fmaxf(f23.x + zc1.x + b0.z, 0.f);
        o0.w = fmaxf(f23.y + zc1.y + b0.w, 0.f);
        o1.x = fmaxf(f45.x + zc2.x + b1.x, 0.f);
        o1.y = fmaxf(f45.y + zc2.y + b1.y, 0.f);
        o1.z = fmaxf(f67.x + zc3.x + b1.z, 0.f);
        o1.w = fmaxf(f67.y + zc3.y + b1.w, 0.f);
        float4* op = (float4*)(o + (size_t)(n0 + j) * OUTC + ch * 8);
        op[0] = o0;
        op[1] = o1;
    }
}

// ---------------- launch ---------------------------------------------------------
extern "C" void kernel_launch(void* const* d_in, const int* in_sizes, int n_in,
                              void* d_out, int out_size) {
    const float* vertices_int = (const float*)d_in[0];
    const float* vertices_nh  = (const float*)d_in[1];
    const int*   nh_indices   = (const int*)d_in[2];
    const int*   int_indices  = (const int*)d_in[3];
    const float* nh_edges     = (const float*)d_in[4];
    const float* int_edges    = (const float*)d_in[5];
    const int*   is_int       = (const int*)d_in[6];
    const float* Wvc_int      = (const float*)d_in[7];
    const float* Wvc_nh       = (const float*)d_in[8];
    const float* Wvn_int      = (const float*)d_in[9];
    const float* Wvn_nh       = (const float*)d_in[10];
    const float* bv_int       = (const float*)d_in[11];
    const float* bv_nh        = (const float*)d_in[12];
    const float* a_int        = (const float*)d_in[13];
    const float* a_nh         = (const float*)d_in[14];
    float* out = (float*)d_out;

    cudaFuncSetAttribute(gemm_kernel,
                         cudaFuncAttributeMaxDynamicSharedMemorySize, GSMEM_BYTES);

    setup_kernel<<<288 + (N_NODES + 255) / 256, 256>>>(
        Wvc_int, Wvn_int, a_int, Wvc_nh, Wvn_nh, a_nh, is_int);

    gemm_kernel<<<GEMM_GRID, 256, GSMEM_BYTES>>>(vertices_int, vertices_nh);

    dim3 wgrid((N_NODES + 255) / 256, 2);
    weight_kernel<<<wgrid, 256>>>(int_indices, nh_indices, int_edges, nh_edges);

    dim3 ggr(N_NODES / GB_NODES, 2);
    gather_kernel<<<ggr, GB_THREADS>>>(bv_int, bv_nh, out);
}

// round 15
// speedup vs baseline: 1.2742x; 1.0121x over previous
#include <cuda_runtime.h>
#include <cuda_fp16.h>
#include <cuda_bf16.h>
#include <cstdint>

#define N_NODES 100000
#define VF      128
#define FILT    64
#define NH      3
#define KNBR    10
#define ZC      192
#define NCOLS   384
#define OUTC    192

// ---------------- scratch (static device globals) --------------------------
__device__ __half         g_Zch[2][(size_t)N_NODES * ZC];   // fp16, compacted
__device__ __nv_bfloat16  g_Znh[2][(size_t)N_NODES * ZC];   // bf16, compacted
__device__ uint32_t       g_Bh[2][(VF / 2) * NCOLS];        // fp16x2 packed [k2][c]
__device__ float          g_w1[2][NH * VF];
__device__ float          g_w2[2][NH * VF];
__device__ int4           g_meta[N_NODES];   // {(pos<<1)|b, s1h0, s1h1, s1h2}
__device__ float4         g_s2v[N_NODES];    // {s2h0, s2h1, s2h2, bits((pos<<1)|b)}
__device__ uint4          g_rec[2][(size_t)N_NODES * KNBR]; // {off, p0, p1, p2}
__device__ float4         g_hdr[2][N_NODES]; // {rs0, rs1, rs2, bits(cg|(pb<<4))}
__device__ int            g_perm[2][N_NODES];
__device__ int            g_cnt[2];          // zero-init; re-zeroed at graph tail

// ---------------- helpers ----------------------------------------------------
__device__ __forceinline__ void mma_f16(float (&d)[4], const uint32_t (&a)[4],
                                        const uint32_t (&b)[2]) {
    asm volatile(
        "mma.sync.aligned.m16n8k16.row.col.f32.f16.f16.f32 "
        "{%0,%1,%2,%3}, {%4,%5,%6,%7}, {%8,%9}, {%0,%1,%2,%3};"
        : "+f"(d[0]), "+f"(d[1]), "+f"(d[2]), "+f"(d[3])
        : "r"(a[0]), "r"(a[1]), "r"(a[2]), "r"(a[3]), "r"(b[0]), "r"(b[1]));
}
__device__ __forceinline__ uint32_t smem_u32(const void* p) {
    uint32_t a;
    asm("{ .reg .u64 t; cvta.to.shared.u64 t, %1; cvt.u32.u64 %0, t; }"
        : "=r"(a) : "l"(p));
    return a;
}
__device__ __forceinline__ void cp_async16(uint32_t saddr, const void* g) {
    asm volatile("cp.async.cg.shared.global [%0], [%1], 16;"
                 :: "r"(saddr), "l"(g) : "memory");
}
#define CP_COMMIT() asm volatile("cp.async.commit_group;" ::: "memory")
#define CP_WAIT(n)  asm volatile("cp.async.wait_group %0;" :: "n"(n) : "memory")
__device__ __forceinline__ uint32_t pack_bf16x2(float lo, float hi) {
    uint32_t r;
    asm("cvt.rn.bf16x2.f32 %0, %1, %2;" : "=r"(r) : "f"(hi), "f"(lo));
    return r;
}
__device__ __forceinline__ uint32_t pack_f16x2(float lo, float hi) {
    __half2 h = __floats2half2_rn(lo, hi);
    return *(uint32_t*)&h;
}
// bf16x2 -> packed f32x2 (low elem in low word)
__device__ __forceinline__ unsigned long long bf2_f32x2(uint32_t u) {
    unsigned long long r;
    uint32_t lo = u << 16;
    uint32_t hi = u & 0xffff0000u;
    asm("mov.b64 %0, {%1, %2};" : "=l"(r) : "r"(lo), "r"(hi));
    return r;
}
#define FMA2(acc, a, b) \
    asm("fma.rn.f32x2 %0, %1, %2, %0;" : "+l"(acc) : "l"(a), "l"(b))

// ---------------- fused setup: prepack | wvec | compact -------------------------
__global__ void setup_kernel(const float* __restrict__ Wvc0, const float* __restrict__ Wvn0,
                             const float* __restrict__ a0,
                             const float* __restrict__ Wvc1, const float* __restrict__ Wvn1,
                             const float* __restrict__ a1,
                             const int* __restrict__ is_int) {
    const int bid = blockIdx.x;
    if (bid < 192) {
        const int branch = bid >= 96;
        const float* Wvc = branch ? Wvc1 : Wvc0;
        const float* Wvn = branch ? Wvn1 : Wvn0;
        int i = (bid - branch * 96) * 256 + threadIdx.x;     // < 24576
        int k2 = i / NCOLS, c = i % NCOLS;
        const float* W;
        int h, o;
        if (c < ZC) { W = Wvc; h = c / FILT; o = c % FILT; }
        else        { W = Wvn; h = (c - ZC) / FILT; o = (c - ZC) % FILT; }
        float v0 = W[((size_t)h * VF + 2 * k2) * FILT + o];
        float v1 = W[((size_t)h * VF + 2 * k2 + 1) * FILT + o];
        g_Bh[branch][i] = pack_f16x2(v0, v1);
    } else if (bid < 288) {
        int w = (bid - 192) * 8 + (threadIdx.x >> 5);        // < 768
        int lane = threadIdx.x & 31;
        const int branch = w >= NH * VF;
        int gw = w - branch * NH * VF;
        int h = gw / VF, k = gw % VF;
        const float* Wvc = branch ? Wvc1 : Wvc0;
        const float* Wvn = branch ? Wvn1 : Wvn0;
        const float* a   = branch ? a1 : a0;
        const float* wn = Wvn + ((size_t)h * VF + k) * FILT;
        const float* wc = Wvc + ((size_t)h * VF + k) * FILT;
        float v1 = wn[lane] * a[h * 128 + lane] + wn[lane + 32] * a[h * 128 + lane + 32];
        float v2 = wc[lane] * a[h * 128 + 64 + lane] + wc[lane + 32] * a[h * 128 + 96 + lane];
#pragma unroll
        for (int o = 16; o; o >>= 1) {
            v1 += __shfl_xor_sync(0xffffffffu, v1, o);
            v2 += __shfl_xor_sync(0xffffffffu, v2, o);
        }
        if (lane == 0) {
            g_w1[branch][h * VF + k] = v1;
            g_w2[branch][h * VF + k] = v2;
        }
    } else {
        // ---- warp-aggregated compaction: 2 atomics per warp, popc ranks ----
        int n = (bid - 288) * 256 + threadIdx.x;
        const int lane = threadIdx.x & 31;
        const bool valid = n < N_NODES;
        int b = -1;
        if (valid) b = (is_int[n] == 1) ? 0 : 1;
        uint32_t m0 = __ballot_sync(0xffffffffu, b == 0);
        uint32_t m1 = __ballot_sync(0xffffffffu, b == 1);
        int base0 = 0, base1 = 0;
        if (lane == 0) {
            base0 = atomicAdd(&g_cnt[0], __popc(m0));
            base1 = atomicAdd(&g_cnt[1], __popc(m1));
        }
        base0 = __shfl_sync(0xffffffffu, base0, 0);
        base1 = __shfl_sync(0xffffffffu, base1, 0);
        if (valid) {
            uint32_t below = (1u << lane) - 1u;
            int pos = (b == 0) ? base0 + __popc(m0 & below)
                               : base1 + __popc(m1 & below);
            g_perm[b][pos] = n;
            g_meta[n].x = (pos << 1) | b;
        }
    }
}

// ---------------- fp16 mma.sync GEMM (m16n8k16) + fused s1/s2 -------------------
#define AS2 68
#define BS2 136
#define A_U32 (128 * AS2)
#define B_BUF_U32 (64 * BS2)
#define GSMEM_BYTES ((A_U32 + 2 * B_BUF_U32) * 4)
#define GEMM_GRID 784

__global__ void __launch_bounds__(256, 2)
gemm_kernel(const float* __restrict__ v_int, const float* __restrict__ v_nh) {
    extern __shared__ uint32_t sm[];
    uint32_t* As = sm;
    uint32_t* Bs0 = sm + A_U32;

    const int cnt0 = g_cnt[0];
    const int nb0 = (cnt0 + 127) >> 7;
    int branch, bm, cnt;
    if ((int)blockIdx.x < nb0) {
        branch = 0; bm = blockIdx.x * 128; cnt = cnt0;
    } else {
        branch = 1; bm = (blockIdx.x - nb0) * 128; cnt = g_cnt[1];
        if (bm >= cnt) return;
    }

    const int tid = threadIdx.x;
    const int lane = tid & 31;
    const int g = lane >> 2;
    const int tg = lane & 3;
    const int wid = tid >> 5;
    const int warp_m = wid & 3;
    const int warp_n = wid >> 2;

    const uint32_t sbB = smem_u32(Bs0);

    {
        const int k2 = tid >> 2;
        const int coff = (tid & 3) * 32;
        const uint32_t* Bsrc = g_Bh[branch] + (size_t)k2 * NCOLS + coff;
        const uint32_t bdst = sbB + (uint32_t)(k2 * BS2 + coff) * 4u;
#pragma unroll
        for (int j = 0; j < 8; j++) cp_async16(bdst + j * 16, Bsrc + j * 4);
        CP_COMMIT();
#pragma unroll
        for (int j = 0; j < 8; j++)
            cp_async16(bdst + B_BUF_U32 * 4 + j * 16, Bsrc + 128 + j * 4);
        CP_COMMIT();
    }

    const int r_row = tid >> 1;
    const int grl = bm + r_row;
    const int nd = g_perm[branch][grl < cnt ? grl : cnt - 1];
    {
        const int ch2 = (tid & 1) * 32;
        const float4* Ag = (const float4*)((branch ? v_nh : v_int) +
                                           (size_t)nd * VF + ch2 * 2);
        uint2* dst = (uint2*)(As + r_row * AS2 + ch2);
#pragma unroll
        for (int j = 0; j < 16; j++) {
            float4 v = Ag[j];
            dst[j] = make_uint2(pack_f16x2(v.x, v.y), pack_f16x2(v.z, v.w));
        }
    }

#pragma unroll 1
    for (int s = 0; s < 3; s++) {
        if (s < 2) { CP_WAIT(1); } else { CP_WAIT(0); }
        __syncthreads();

        const uint32_t* Bs = Bs0 + (s & 1) * B_BUF_U32;

        float acc[2][8][4];
#pragma unroll
        for (int mt = 0; mt < 2; mt++)
#pragma unroll
            for (int nt = 0; nt < 8; nt++)
#pragma unroll
                for (int q = 0; q < 4; q++) acc[mt][nt][q] = 0.f;

        const int ar = warp_m * 32 + g;
        const int cb = warp_n * 64 + g;
#pragma unroll
        for (int k2_0 = 0; k2_0 < 64; k2_0 += 8) {
            uint32_t a[2][4];
#pragma unroll
            for (int mt = 0; mt < 2; mt++) {
                const uint32_t* ap = As + (ar + mt * 16) * AS2 + k2_0 + tg;
                a[mt][0] = ap[0];
                a[mt][1] = ap[8 * AS2];
                a[mt][2] = ap[4];
                a[mt][3] = ap[8 * AS2 + 4];
            }
            uint32_t b[8][2];
            const uint32_t* bp0 = Bs + (k2_0 + tg) * BS2 + cb;
            const uint32_t* bp1 = bp0 + 4 * BS2;
#pragma unroll
            for (int nt = 0; nt < 8; nt++) {
                b[nt][0] = bp0[nt * 8];
                b[nt][1] = bp1[nt * 8];
            }
#pragma unroll
            for (int mt = 0; mt < 2; mt++)
#pragma unroll
                for (int nt = 0; nt < 8; nt++)
                    mma_f16(acc[mt][nt], a[mt], b[nt]);
        }

        __syncthreads();

        if (s == 0) {
            const int k2 = tid >> 2;
            const int coff = (tid & 3) * 32;
            const uint32_t* Bsrc = g_Bh[branch] + (size_t)k2 * NCOLS + 256 + coff;
            const uint32_t bdst = sbB + (uint32_t)(k2 * BS2 + coff) * 4u;
#pragma unroll
            for (int j = 0; j < 8; j++) cp_async16(bdst + j * 16, Bsrc + j * 4);
            CP_COMMIT();
        }

        // ---- epilogue: both Zc (fp16) and Zn (bf16) are 16-bit packed ----
        const int cbase = s * 128 + warp_n * 64;
        const bool isZc = cbase < ZC;
        const int coff = isZc ? cbase : cbase - ZC;
        uint32_t* zb = isZc ? (uint32_t*)g_Zch[branch] : (uint32_t*)g_Znh[branch];
#pragma unroll
        for (int mt = 0; mt < 2; mt++) {
            const int r0 = warp_m * 32 + mt * 16 + g;
            const int gr0 = bm + r0, gr1 = gr0 + 8;
            uint32_t* row0 = zb + ((size_t)gr0 * ZC + coff) / 2 + tg;
            uint32_t* row1 = zb + ((size_t)gr1 * ZC + coff) / 2 + tg;
            const bool ok0 = gr0 < cnt, ok1 = gr1 < cnt;
#pragma unroll
            for (int nt = 0; nt < 8; nt++) {
                uint32_t p0 = isZc ? pack_f16x2(acc[mt][nt][0], acc[mt][nt][1])
                                   : pack_bf16x2(acc[mt][nt][0], acc[mt][nt][1]);
                uint32_t p1 = isZc ? pack_f16x2(acc[mt][nt][2], acc[mt][nt][3])
                                   : pack_bf16x2(acc[mt][nt][2], acc[mt][nt][3]);
                if (ok0) row0[nt * 4] = p0;
                if (ok1) row1[nt * 4] = p1;
            }
        }
    }

    // ---- fused s1/s2 from fp16 A tile ----
    float* wsv = (float*)Bs0;
    for (int i = tid; i < 6 * 128; i += 256) {
        int d = i >> 7, k = i & 127;
        wsv[d * 132 + k] = (d < 3) ? g_w1[branch][d * 128 + k]
                                   : g_w2[branch][(d - 3) * 128 + k];
    }
    __syncthreads();
    {
        const int dset = (tid & 1) * 3;
        const __half2* arow = (const __half2*)(As + r_row * AS2);
        const float* w0 = wsv + (dset + 0) * 132;
        const float* w1 = wsv + (dset + 1) * 132;
        const float* w2 = wsv + (dset + 2) * 132;
        float s0 = 0.f, s1 = 0.f, s2 = 0.f;
#pragma unroll 8
        for (int k2 = 0; k2 < 64; k2++) {
            float2 av = __half22float2(arow[k2]);
            s0 += av.x * w0[2 * k2] + av.y * w0[2 * k2 + 1];
            s1 += av.x * w1[2 * k2] + av.y * w1[2 * k2 + 1];
            s2 += av.x * w2[2 * k2] + av.y * w2[2 * k2 + 1];
        }
        if (grl < cnt) {
            if (tid & 1) {
                g_s2v[nd] = make_float4(s0, s1, s2,
                                        __int_as_float((grl << 1) | branch));
            } else {
                float* mp = (float*)&g_meta[nd];
                mp[1] = s0; mp[2] = s1; mp[3] = s2;
            }
        }
    }
}

// ---------------- weight kernel: one THREAD per (node, branch) -----------------
__global__ __launch_bounds__(256)
void weight_kernel(const int* __restrict__ idx_int, const int* __restrict__ idx_nh,
                   const float* __restrict__ e_int, const float* __restrict__ e_nh) {
    const int branch = blockIdx.y;
    const int* __restrict__ idx   = branch ? idx_nh : idx_int;
    const float* __restrict__ edg = branch ? e_nh : e_int;

    int n = blockIdx.x * 256 + threadIdx.x;
    if (n >= N_NODES) return;

    int iv[KNBR];
    float ev[KNBR];
    const int2* ip = (const int2*)(idx + (size_t)n * KNBR);
    const float2* ep = (const float2*)(edg + (size_t)n * KNBR);
#pragma unroll
    for (int j = 0; j < 5; j++) {
        int2 a = ip[j];   iv[2 * j] = a.x; iv[2 * j + 1] = a.y;
        float2 b = ep[j]; ev[2 * j] = b.x; ev[2 * j + 1] = b.y;
    }

    float4 sv = g_s2v[n];
    const int pb = __float_as_int(sv.w);
    const bool nact = (pb & 1) == branch;
    const float s20 = nact ? sv.x : 0.f;
    const float s21 = nact ? sv.y : 0.f;
    const float s22 = nact ? sv.z : 0.f;

    uint4* rec = g_rec[branch] + (size_t)n * KNBR;
    float ps0 = 0.f, ps1 = 0.f, ps2 = 0.f;
    int cg = 0, nbcnt = 0;

#pragma unroll
    for (int c = 0; c < 2; c++) {
        int4 m[5];
        bool val[5];
#pragma unroll
        for (int j = 0; j < 5; j++) {            // unconditional clamped loads
            int i = iv[c * 5 + j];
            val[j] = (i >= 0);
            m[j] = g_meta[val[j] ? i : 0];
        }
#pragma unroll
        for (int j = 0; j < 5; j++) {
            int k = c * 5 + j;
            if (val[j]) {
                nbcnt++;
                bool gk = (m[j].x & 1) == branch;
                float s10 = gk ? __int_as_float(m[j].y) : 0.f;
                float s11 = gk ? __int_as_float(m[j].z) : 0.f;
                float s12 = gk ? __int_as_float(m[j].w) : 0.f;
                float p0 = __expf((s10 + s20) * ev[k]);
                float p1 = __expf((s11 + s21) * ev[k]);
                float p2 = __expf((s12 + s22) * ev[k]);
                ps0 += p0; ps1 += p1; ps2 += p2;
                if (gk) {
                    rec[cg] = make_uint4((uint32_t)((m[j].x >> 1) * (ZC * 2)),
                                         __float_as_uint(p0), __float_as_uint(p1),
                                         __float_as_uint(p2));
                    cg++;
                }
            } else {
                ps0 += 1.f; ps1 += 1.f; ps2 += 1.f;   // padded slot: exp(0)
            }
        }
    }

    float inv = 1.f / fmaxf((float)nbcnt, 1.f);
    g_hdr[branch][n] = make_float4(__fdividef(inv, ps0), __fdividef(inv, ps1),
                                   __fdividef(inv, ps2),
                                   __int_as_float(cg | (pb << 4)));
}

// ---------------- gather kernel: flat (node, channel-group) mapping ------------
// 240 threads / 10 nodes per block; thread = (node j, ch 0..23).
// Unroll-by-2 (MLP=2), weights pre-duplicated in smem (LDS.64, no dup-mov).
#define GB_NODES 10
#define GB_THREADS 240

__global__ __launch_bounds__(GB_THREADS)
void gather_kernel(const float* __restrict__ bv_int, const float* __restrict__ bv_nh,
                   float* __restrict__ out) {
    const int branch = blockIdx.y;
    const float* __restrict__ bv = branch ? bv_nh : bv_int;
    float* __restrict__ o = out + (size_t)branch * N_NODES * OUTC;

    if (blockIdx.x == 0 && blockIdx.y == 0 && threadIdx.x == 0) {
        g_cnt[0] = 0;   // reset for next graph replay
        g_cnt[1] = 0;
    }

    __shared__ int    soff[GB_NODES][KNBR];
    __shared__ float2 swt2[GB_NODES][NH][KNBR];   // duplicated weights {w,w}
    __shared__ float  srs[GB_NODES][NH];
    __shared__ int    scg[GB_NODES];
    __shared__ int    spb[GB_NODES];

    const int tid = threadIdx.x;
    const int n0 = blockIdx.x * GB_NODES;

    // stage headers
    if (tid < GB_NODES) {
        float4 hdr = g_hdr[branch][n0 + tid];
        int w = __float_as_int(hdr.w);
        scg[tid] = w & 15;
        spb[tid] = w >> 4;
        srs[tid][0] = hdr.x;
        srs[tid][1] = hdr.y;
        srs[tid][2] = hdr.z;
    }
    __syncthreads();

    // stage records (normalizer folded in, weights duplicated)
    if (tid < GB_NODES * KNBR) {
        int j = tid / KNBR, s = tid % KNBR;
        if (s < scg[j]) {
            uint4 r = g_rec[branch][(size_t)(n0 + j) * KNBR + s];
            soff[j][s] = (int)r.x;
            float w0 = __uint_as_float(r.y) * srs[j][0];
            float w1 = __uint_as_float(r.z) * srs[j][1];
            float w2 = __uint_as_float(r.w) * srs[j][2];
            swt2[j][0][s] = make_float2(w0, w0);
            swt2[j][1][s] = make_float2(w1, w1);
            swt2[j][2][s] = make_float2(w2, w2);
        }
    }
    __syncthreads();

    // gather: every thread active; unroll-by-2 for MLP
    const int j = tid / 24;
    const int ch = tid - j * 24;
    const int myh = ch >> 3;
    const int cg = scg[j];

    unsigned long long a01 = 0, a23 = 0, a45 = 0, a67 = 0;
    const char* __restrict__ Zb = (const char*)g_Znh[branch];
    const int ch16 = ch * 16;
    const float2* __restrict__ wrow = swt2[j][myh];
    const int* __restrict__ orow = soff[j];

    int k = 0;
#pragma unroll 1
    for (; k + 2 <= cg; k += 2) {
        int off0 = orow[k];
        int off1 = orow[k + 1];
        unsigned long long w0 = *(const unsigned long long*)&wrow[k];
        unsigned long long w1 = *(const unsigned long long*)&wrow[k + 1];
        uint4 v0 = *(const uint4*)(Zb + off0 + ch16);
        uint4 v1 = *(const uint4*)(Zb + off1 + ch16);
        FMA2(a01, w0, bf2_f32x2(v0.x));
        FMA2(a23, w0, bf2_f32x2(v0.y));
        FMA2(a45, w0, bf2_f32x2(v0.z));
        FMA2(a67, w0, bf2_f32x2(v0.w));
        FMA2(a01, w1, bf2_f32x2(v1.x));
        FMA2(a23, w1, bf2_f32x2(v1.y));
        FMA2(a45, w1, bf2_f32x2(v1.z));
        FMA2(a67, w1, bf2_f32x2(v1.w));
    }
    if (k < cg) {
        int off0 = orow[k];
        unsigned long long w0 = *(const unsigned long long*)&wrow[k];
        uint4 v0 = *(const uint4*)(Zb + off0 + ch16);
        FMA2(a01, w0, bf2_f32x2(v0.x));
        FMA2(a23, w0, bf2_f32x2(v0.y));
        FMA2(a45, w0, bf2_f32x2(v0.z));
        FMA2(a67, w0, bf2_f32x2(v0.w));
    }

    {
        const int pb = spb[j];
        const bool nact = (pb & 1) == branch;
        const int pos_self = pb >> 1;
        float2 f01 = *(float2*)&a01;
        float2 f23 = *(float2*)&a23;
        float2 f45 = *(float2*)&a45;
        float2 f67 = *(float2*)&a67;
        float2 zc0 = make_float2(0.f, 0.f), zc1 = zc0, zc2 = zc0, zc3 = zc0;
        if (nact) {
            uint4 zc = *(const uint4*)(g_Zch[branch] + (size_t)pos_self * ZC + ch * 8);
            zc0 = __half22float2(*(__half2*)&zc.x);
            zc1 = __half22float2(*(__half2*)&zc.y);
            zc2 = __half22float2(*(__half2*)&zc.z);
            zc3 = __half22float2(*(__half2*)&zc.w);
        }
        const float4* bvp = (const float4*)(bv + ch * 8);
        float4 b0 = bvp[0], b1 = bvp[1];
        float4 o0, o1;
        o0.x = fmaxf(f01.x + zc0.x + b0.x, 0.f);
        o0.y = fmaxf(f01.y + zc0.y + b0.y, 0.f);
        o0.z = fmaxf(f23.x + zc1.x + b0.z, 0.f);
        o0.w = fmaxf(f23.y + zc1.y + b0.w, 0.f);
        o1.x = fmaxf(f45.x + zc2.x + b1.x, 0.f);
        o1.y = fmaxf(f45.y + zc2.y + b1.y, 0.f);
        o1.z = fmaxf(f67.x + zc3.x + b1.z, 0.f);
        o1.w = fmaxf(f67.y + zc3.y + b1.w, 0.f);
        float4* op = (float4*)(o + (size_t)(n0 + j) * OUTC + ch * 8);
        op[0] = o0;
        op[1] = o1;
    }
}

// ---------------- launch ---------------------------------------------------------
extern "C" void kernel_launch(void* const* d_in, const int* in_sizes, int n_in,
                              void* d_out, int out_size) {
    const float* vertices_int = (const float*)d_in[0];
    const float* vertices_nh  = (const float*)d_in[1];
    const int*   nh_indices   = (const int*)d_in[2];
    const int*   int_indices  = (const int*)d_in[3];
    const float* nh_edges     = (const float*)d_in[4];
    const float* int_edges    = (const float*)d_in[5];
    const int*   is_int       = (const int*)d_in[6];
    const float* Wvc_int      = (const float*)d_in[7];
    const float* Wvc_nh       = (const float*)d_in[8];
    const float* Wvn_int      = (const float*)d_in[9];
    const float* Wvn_nh       = (const float*)d_in[10];
    const float* bv_int       = (const float*)d_in[11];
    const float* bv_nh        = (const float*)d_in[12];
    const float* a_int        = (const float*)d_in[13];
    const float* a_nh         = (const float*)d_in[14];
    float* out = (float*)d_out;

    cudaFuncSetAttribute(gemm_kernel,
                         cudaFuncAttributeMaxDynamicSharedMemorySize, GSMEM_BYTES);

    setup_kernel<<<288 + (N_NODES + 255) / 256, 256>>>(
        Wvc_int, Wvn_int, a_int, Wvc_nh, Wvn_nh, a_nh, is_int);

    gemm_kernel<<<GEMM_GRID, 256, GSMEM_BYTES>>>(vertices_int, vertices_nh);

    dim3 wgrid((N_NODES + 255) / 256, 2);
    weight_kernel<<<wgrid, 256>>>(int_indices, nh_indices, int_edges, nh_edges);

    dim3 ggr(N_NODES / GB_NODES, 2);
    gather_kernel<<<ggr, GB_THREADS>>>(bv_int, bv_nh, out);
}